// round 5
// baseline (speedup 1.0000x reference)
#include <cuda_runtime.h>
#include <cstdint>

// Problem constants
#define NN 50000
#define DD 128
#define EE 800000
#define ND (NN*DD)
#define TB 256
#define K1 25000
#define K2 12500
#define PREP_GRID 196   // ceil(NN/256)

// ----------------------------------------------------------------------------
// Device scratch (allocation-free: __device__ globals)
// ----------------------------------------------------------------------------
__device__ float g_h[ND];
__device__ float g_t[ND];
__device__ float g_g[ND];
__device__ float g_xx[ND];
__device__ float g_d0[ND];
__device__ float g_d1[ND];
__device__ int   g_nbrr[EE];
__device__ int   g_nbrc[EE];
__device__ float g_ecc0[EE];
__device__ float g_ecc1[EE];
__device__ float g_ecc2[EE];
__device__ float g_ctc0[EE];
__device__ float g_ctc1[EE];
__device__ float g_ctr0[EE];
__device__ float g_ctr1[EE];
__device__ float g_dis[NN];
__device__ float g_normed[NN];
__device__ float g_aggr[NN];
__device__ float g_w[NN];
__device__ float g_nm[NN];
__device__ float g_score[NN];
__device__ float g_s[NN];
__device__ unsigned int g_hist[65536];
__device__ unsigned long long g_prefix;
__device__ int g_k;
__device__ float g_pinv[2];
__device__ int g_cntr[NN];
__device__ int g_cntc[NN];
__device__ int g_offr[NN + 1];
__device__ int g_offc[NN + 1];
__device__ int g_curr[NN];
__device__ int g_curc[NN];
__device__ int g_act0[NN];
__device__ int g_act1[NN];
__device__ int g_acnt0;
__device__ int g_acnt1;
// software grid barrier
__device__ int g_barcnt;
__device__ unsigned g_bargen;

// ----------------------------------------------------------------------------
// f32x2 packed-FMA helpers
// ----------------------------------------------------------------------------
__device__ __forceinline__ unsigned long long fma2(unsigned long long a,
                                                   unsigned long long b,
                                                   unsigned long long c) {
    unsigned long long d;
    asm("fma.rn.f32x2 %0, %1, %2, %3;" : "=l"(d) : "l"(a), "l"(b), "l"(c));
    return d;
}
__device__ __forceinline__ unsigned long long pack2(float x) {
    unsigned long long d;
    asm("mov.b64 %0, {%1, %1};" : "=l"(d) : "f"(x));
    return d;
}
__device__ __forceinline__ float2 unpack2(unsigned long long v) {
    float2 r;
    asm("mov.b64 {%0, %1}, %2;" : "=f"(r.x), "=f"(r.y) : "l"(v));
    return r;
}

// ----------------------------------------------------------------------------
// Software grid barrier (all blocks must be co-resident; grids <= 196 blocks)
// ----------------------------------------------------------------------------
__device__ __forceinline__ void gridbar() {
    __syncthreads();
    if (threadIdx.x == 0) {
        unsigned gen = *((volatile unsigned*)&g_bargen);
        __threadfence();
        int ticket = atomicAdd(&g_barcnt, 1);
        if (ticket == (int)gridDim.x - 1) {
            g_barcnt = 0;
            __threadfence();
            atomicAdd(&g_bargen, 1u);
        } else {
            while (*((volatile unsigned*)&g_bargen) == gen) {}
        }
        __threadfence();
    }
    __syncthreads();
}

// ----------------------------------------------------------------------------
// init
// ----------------------------------------------------------------------------
__global__ void k_init(const float* __restrict__ pvec) {
    int i = blockIdx.x * blockDim.x + threadIdx.x;   // 65536 threads
    if (i < 65536) g_hist[i] = 0u;
    if (i < NN) { g_nm[i] = 1.0f; g_w[i] = 1.0f; g_cntr[i] = 0; g_cntc[i] = 0; }
    if (i == 0) { g_acnt0 = 0; g_acnt1 = 0; g_barcnt = 0; g_bargen = 0u; }
    if (blockIdx.x == 0 && threadIdx.x < 64) {
        int l = threadIdx.x >> 5, lane = threadIdx.x & 31;
        float4 p = ((const float4*)(pvec + l * DD))[lane];
        float s = p.x*p.x + p.y*p.y + p.z*p.z + p.w*p.w;
        #pragma unroll
        for (int o = 16; o; o >>= 1) s += __shfl_xor_sync(0xffffffffu, s, o);
        if (lane == 0) g_pinv[l] = rsqrtf(s);
    }
}

// ----------------------------------------------------------------------------
// CSR build
// ----------------------------------------------------------------------------
__global__ void k_csr_hist(const int* __restrict__ ei) {
    int e = blockIdx.x * blockDim.x + threadIdx.x;
    if (e >= EE) return;
    atomicAdd(&g_cntr[ei[e]], 1);
    atomicAdd(&g_cntc[ei[EE + e]], 1);
}

__device__ void scan_one(const int* __restrict__ cnt, int* __restrict__ off,
                         int* __restrict__ cur, int* part) {
    const int PER = 49;
    int t = threadIdx.x;
    int base = t * PER;
    int s = 0;
    for (int i = 0; i < PER; i++) { int idx = base + i; if (idx < NN) s += cnt[idx]; }
    part[t] = s;
    __syncthreads();
    if (t == 0) {
        int acc = 0;
        for (int i = 0; i < 1024; i++) { int v = part[i]; part[i] = acc; acc += v; }
        off[NN] = acc;
    }
    __syncthreads();
    int run = part[t];
    for (int i = 0; i < PER; i++) {
        int idx = base + i;
        if (idx < NN) { off[idx] = run; cur[idx] = run; run += cnt[idx]; }
    }
}

__global__ void k_scan2() {
    __shared__ int part[1024];
    scan_one(g_cntr, g_offr, g_curr, part);
    __syncthreads();
    scan_one(g_cntc, g_offc, g_curc, part);
}

__global__ void k_csr_fill(const int* __restrict__ ei) {
    int e = blockIdx.x * blockDim.x + threadIdx.x;
    if (e >= EE) return;
    int r = ei[e], c = ei[EE + e];
    int pr = atomicAdd(&g_curr[r], 1);
    g_nbrr[pr] = c;
    int pc = atomicAdd(&g_curc[c], 1);
    g_nbrc[pc] = r;
}

// ----------------------------------------------------------------------------
// Fused level prep: deg -> [bar] -> coef_col -> [bar] -> coef_row
// Launch with exactly PREP_GRID blocks of TB threads.
// ----------------------------------------------------------------------------
__global__ void __launch_bounds__(TB) k_prep(float* __restrict__ ecc,
                                             float* __restrict__ ctc,
                                             float* __restrict__ ctr) {
    int v = blockIdx.x * blockDim.x + threadIdx.x;
    // phase 1: deg
    if (v < NN) {
        int s = g_offr[v], e = g_offr[v + 1];
        float sum = 0.f;
        for (int i = s; i < e; i++) sum += g_nm[g_nbrr[i]];
        float d = g_nm[v] * sum;
        float dis_, nrm;
        if (d > 0.f) { dis_ = rsqrtf(d); nrm = g_w[v] / d; }
        else         { dis_ = 0.f; nrm = 0.f; }
        g_dis[v] = dis_;
        g_normed[v] = nrm;
    }
    gridbar();
    // phase 2: coef_col (aggr, ecc, ctc)
    if (v < NN) {
        int c = v;
        int s = g_offc[c], e = g_offc[c + 1];
        float nmc = g_nm[c], disc = g_dis[c];
        float ag = 0.f;
        for (int i = s; i < e; i++) {
            int r = g_nbrc[i];
            ag = fmaf(g_normed[r], g_nm[r], ag);
        }
        float aggr = fmaf(nmc, ag, 1e-12f);
        g_aggr[c] = aggr;
        float inv = nmc / aggr;
        for (int i = s; i < e; i++) {
            int r = g_nbrc[i];
            ecc[i] = g_dis[r] * disc;
            if (ctc) ctc[i] = g_normed[r] * g_nm[r] * inv;
        }
    }
    if (!ctr) return;
    gridbar();
    // phase 3: coef_row
    if (v < NN) {
        int r = v;
        int s = g_offr[r], e = g_offr[r + 1];
        float base = g_normed[r] * g_nm[r];
        for (int i = s; i < e; i++) {
            int c = g_nbrr[i];
            ctr[i] = base * g_nm[c] / g_aggr[c];
        }
    }
}

// ----------------------------------------------------------------------------
// Fused top-k: keys (in regs) + 4x(count, scan) + applynode/compaction.
// Launch with exactly PREP_GRID blocks of TB threads.
// ----------------------------------------------------------------------------
__global__ void __launch_bounds__(TB) k_topk(int kval, int* __restrict__ act,
                                             int* __restrict__ acnt) {
    __shared__ unsigned sf[TB];
    int v = blockIdx.x * blockDim.x + threadIdx.x;
    int t = threadIdx.x;

    if (v == 0) { g_prefix = 0ull; g_k = kval; }

    unsigned long long key = 0ull;
    bool valid = (v < NN);
    if (valid) {
        float s = (g_nm[v] > 0.f) ? g_score[v] : __int_as_float(0xff800000);
        unsigned u = __float_as_uint(s);
        u = (u & 0x80000000u) ? ~u : (u | 0x80000000u);
        key = ((unsigned long long)u << 32) |
              (unsigned long long)(0xFFFFFFFFu - (unsigned)v);
    }

    for (int pass = 0; pass < 4; pass++) {
        if (valid) {
            bool in = true;
            if (pass) in = ((key >> (64 - 16 * pass)) == g_prefix);
            if (in) {
                unsigned d = (unsigned)(key >> (48 - 16 * pass)) & 0xFFFFu;
                atomicAdd(&g_hist[d], 1u);
            }
        }
        gridbar();
        if (blockIdx.x == 0) {
            unsigned s = 0;
            #pragma unroll 8
            for (int b = 0; b < 256; b++) s += g_hist[t * 256 + b];
            sf[t] = s;
            __syncthreads();
            for (int off = 1; off < 256; off <<= 1) {
                unsigned vv = sf[t];
                unsigned ad = (t + off < 256) ? sf[t + off] : 0u;
                __syncthreads();
                sf[t] = vv + ad;
                __syncthreads();
            }
            unsigned k = (unsigned)g_k;
            unsigned above = (t < 255) ? sf[t + 1] : 0u;
            if (above < k && sf[t] >= k) {
                unsigned cum = above;
                int d = 0;
                for (int b = 255; b >= 0; b--) {
                    unsigned h = g_hist[t * 256 + b];
                    if (cum + h >= k) { d = t * 256 + b; break; }
                    cum += h;
                }
                g_prefix = (g_prefix << 16) | (unsigned long long)(unsigned)d;
                g_k = (int)(k - cum);
            }
            __syncthreads();
            #pragma unroll 8
            for (int b = 0; b < 256; b++) g_hist[t * 256 + b] = 0u;
        }
        gridbar();
    }

    if (valid) {
        bool kept = (key >= g_prefix);
        g_nm[v] = kept ? 1.f : 0.f;
        g_w[v]  = kept ? g_aggr[v] : 0.f;
        g_s[v]  = kept ? tanhf(g_score[v]) : 0.f;
        if (kept) {
            int slot = atomicAdd(acnt, 1);
            act[slot] = v;
        }
    }
}

// ----------------------------------------------------------------------------
// CSR pull-gather (warp per node, float4 per lane); optional node list.
// ----------------------------------------------------------------------------
template<bool SKIP, bool ADDIN, bool SCORE>
__global__ void __launch_bounds__(256) k_gather_t(
    const float* __restrict__ src, float* __restrict__ dst,
    const int* __restrict__ off, const int* __restrict__ nbr,
    const float* __restrict__ cf, const float* __restrict__ addin,
    const float* __restrict__ pv, int lvl,
    const int* __restrict__ list, int nlist) {
    int wid = (blockIdx.x * blockDim.x + threadIdx.x) >> 5;
    if (wid >= nlist) return;
    int v = list ? list[wid] : wid;
    int lane = threadIdx.x & 31;
    int s = off[v], e = off[v + 1];
    float ax = 0.f, ay = 0.f, az = 0.f, aw = 0.f;
    int i = s;
    if (!SKIP) {
        int e8 = s + ((e - s) & ~7);
        for (; i < e8; i += 8) {
            int n[8]; float w[8]; float4 t[8];
            #pragma unroll
            for (int u = 0; u < 8; u++) { n[u] = nbr[i + u]; w[u] = cf[i + u]; }
            #pragma unroll
            for (int u = 0; u < 8; u++)
                t[u] = ((const float4*)src)[(size_t)n[u] * 32 + lane];
            #pragma unroll
            for (int u = 0; u < 8; u++) {
                ax = fmaf(w[u], t[u].x, ax); ay = fmaf(w[u], t[u].y, ay);
                az = fmaf(w[u], t[u].z, az); aw = fmaf(w[u], t[u].w, aw);
            }
        }
    } else {
        for (; i + 4 <= e; i += 4) {
            int   n0 = nbr[i],   n1 = nbr[i+1],   n2 = nbr[i+2],   n3 = nbr[i+3];
            float w0 = cf[i],    w1 = cf[i+1],    w2 = cf[i+2],    w3 = cf[i+3];
            if (w0 != 0.f) {
                float4 t = ((const float4*)src)[(size_t)n0 * 32 + lane];
                ax = fmaf(w0, t.x, ax); ay = fmaf(w0, t.y, ay);
                az = fmaf(w0, t.z, az); aw = fmaf(w0, t.w, aw);
            }
            if (w1 != 0.f) {
                float4 t = ((const float4*)src)[(size_t)n1 * 32 + lane];
                ax = fmaf(w1, t.x, ax); ay = fmaf(w1, t.y, ay);
                az = fmaf(w1, t.z, az); aw = fmaf(w1, t.w, aw);
            }
            if (w2 != 0.f) {
                float4 t = ((const float4*)src)[(size_t)n2 * 32 + lane];
                ax = fmaf(w2, t.x, ax); ay = fmaf(w2, t.y, ay);
                az = fmaf(w2, t.z, az); aw = fmaf(w2, t.w, aw);
            }
            if (w3 != 0.f) {
                float4 t = ((const float4*)src)[(size_t)n3 * 32 + lane];
                ax = fmaf(w3, t.x, ax); ay = fmaf(w3, t.y, ay);
                az = fmaf(w3, t.z, az); aw = fmaf(w3, t.w, aw);
            }
        }
    }
    for (; i < e; i++) {
        int n = nbr[i]; float w = cf[i];
        if (!SKIP || w != 0.f) {
            float4 t = ((const float4*)src)[(size_t)n * 32 + lane];
            ax = fmaf(w, t.x, ax); ay = fmaf(w, t.y, ay);
            az = fmaf(w, t.z, az); aw = fmaf(w, t.w, aw);
        }
    }
    if (ADDIN) {
        float4 a = ((const float4*)addin)[(size_t)v * 32 + lane];
        ax += a.x; ay += a.y; az += a.z; aw += a.w;
    }
    ((float4*)dst)[(size_t)v * 32 + lane] = make_float4(ax, ay, az, aw);
    if (SCORE) {
        float4 p = ((const float4*)pv)[lane];
        float sdot = ax*p.x + ay*p.y + az*p.z + aw*p.w;
        #pragma unroll
        for (int o = 16; o; o >>= 1) sdot += __shfl_xor_sync(0xffffffffu, sdot, o);
        if (lane == 0) g_score[v] = sdot * g_pinv[lvl];
    }
}

// ----------------------------------------------------------------------------
// Dense GEMM: 64-row tile, 256 threads, per-thread 4x8, FFMA2, k-step 4.
// smem = 64KB (W) + 64*132*4 (A) = 97KB -> 2 blocks/SM.
// ----------------------------------------------------------------------------
#define GEMM_SMEM (128*128*4 + 64*132*4)
__global__ void __launch_bounds__(256, 2) k_gemm(const float* __restrict__ A,
                                                 const float* __restrict__ W,
                                                 const float* __restrict__ bias,
                                                 float* __restrict__ C,
                                                 const float* __restrict__ scale,
                                                 const int* __restrict__ rowidx,
                                                 int m) {
    extern __shared__ float sm[];
    float* sW = sm;              // [128][128]
    float* sA = sm + 128 * 128;  // [64][132]
    const int tid = threadIdx.x;
    const int row0 = blockIdx.x * 64;

    #pragma unroll 4
    for (int i = tid; i < 128 * 32; i += 256) {
        int r = i >> 5, c = (i & 31) << 2;
        *(float4*)(sW + r * 128 + c) = *(const float4*)(W + r * 128 + c);
    }
    #pragma unroll 2
    for (int i = tid; i < 64 * 32; i += 256) {
        int r = i >> 5, c = (i & 31) << 2;
        int rl = row0 + r;
        float4 v = make_float4(0.f, 0.f, 0.f, 0.f);
        if (rl < m) {
            int row = rowidx ? rowidx[rl] : rl;
            v = *(const float4*)(A + (size_t)row * DD + c);
            if (scale) {
                float sc = scale[row];
                v.x *= sc; v.y *= sc; v.z *= sc; v.w *= sc;
            }
        }
        *(float4*)(sA + r * 132 + c) = v;
    }
    __syncthreads();

    const int tx = tid & 15, ty = tid >> 4;
    const int rb = ty * 4, cb = tx * 8;
    unsigned long long acc[4][4] = {};

    #pragma unroll 4
    for (int k0 = 0; k0 < 128; k0 += 4) {
        float av[4][4];
        #pragma unroll
        for (int r = 0; r < 4; r++)
            *(float4*)av[r] = *(float4*)(sA + (rb + r) * 132 + k0);
        #pragma unroll
        for (int kk = 0; kk < 4; kk++) {
            ulonglong2 w0 = *(ulonglong2*)(sW + (k0 + kk) * 128 + cb);
            ulonglong2 w1 = *(ulonglong2*)(sW + (k0 + kk) * 128 + cb + 4);
            #pragma unroll
            for (int r = 0; r < 4; r++) {
                unsigned long long aa = pack2(av[r][kk]);
                acc[r][0] = fma2(aa, w0.x, acc[r][0]);
                acc[r][1] = fma2(aa, w0.y, acc[r][1]);
                acc[r][2] = fma2(aa, w1.x, acc[r][2]);
                acc[r][3] = fma2(aa, w1.y, acc[r][3]);
            }
        }
    }

    float4 b0 = *(const float4*)(bias + cb);
    float4 b1 = *(const float4*)(bias + cb + 4);
    #pragma unroll
    for (int r = 0; r < 4; r++) {
        int rl = row0 + rb + r;
        if (rl < m) {
            int row = rowidx ? rowidx[rl] : rl;
            float2 p0 = unpack2(acc[r][0]);
            float2 p1 = unpack2(acc[r][1]);
            float2 p2 = unpack2(acc[r][2]);
            float2 p3 = unpack2(acc[r][3]);
            float4 o0 = make_float4(p0.x + b0.x, p0.y + b0.y, p1.x + b0.z, p1.y + b0.w);
            float4 o1 = make_float4(p2.x + b1.x, p2.y + b1.y, p3.x + b1.z, p3.y + b1.w);
            *(float4*)(C + (size_t)row * DD + cb)     = o0;
            *(float4*)(C + (size_t)row * DD + cb + 4) = o1;
        }
    }
}

// ----------------------------------------------------------------------------
// Host orchestration
// ----------------------------------------------------------------------------
extern "C" void kernel_launch(void* const* d_in, const int* in_sizes, int n_in,
                              void* d_out, int out_size) {
    const float* x_in = (const float*)d_in[0];
    const int*   ei   = (const int*)d_in[1];
    const float* Wd   = (const float*)d_in[2];
    const float* bd   = (const float*)d_in[3];
    const float* Wu   = (const float*)d_in[4];
    const float* bu   = (const float*)d_in[5];
    const float* Wb   = (const float*)d_in[6];
    const float* bb   = (const float*)d_in[7];
    const float* pvec = (const float*)d_in[8];
    float* out = (float*)d_out;

    float *p_h, *p_t, *p_g, *p_x, *p_d0, *p_d1;
    float *p_ecc0, *p_ecc1, *p_ecc2, *p_ctc0, *p_ctc1, *p_ctr0, *p_ctr1, *p_s;
    int *p_offr, *p_offc, *p_nbrr, *p_nbrc, *p_act0, *p_act1, *p_acnt0, *p_acnt1;
    cudaGetSymbolAddress((void**)&p_h, g_h);
    cudaGetSymbolAddress((void**)&p_t, g_t);
    cudaGetSymbolAddress((void**)&p_g, g_g);
    cudaGetSymbolAddress((void**)&p_x, g_xx);
    cudaGetSymbolAddress((void**)&p_d0, g_d0);
    cudaGetSymbolAddress((void**)&p_d1, g_d1);
    cudaGetSymbolAddress((void**)&p_ecc0, g_ecc0);
    cudaGetSymbolAddress((void**)&p_ecc1, g_ecc1);
    cudaGetSymbolAddress((void**)&p_ecc2, g_ecc2);
    cudaGetSymbolAddress((void**)&p_ctc0, g_ctc0);
    cudaGetSymbolAddress((void**)&p_ctc1, g_ctc1);
    cudaGetSymbolAddress((void**)&p_ctr0, g_ctr0);
    cudaGetSymbolAddress((void**)&p_ctr1, g_ctr1);
    cudaGetSymbolAddress((void**)&p_s, g_s);
    cudaGetSymbolAddress((void**)&p_offr, g_offr);
    cudaGetSymbolAddress((void**)&p_offc, g_offc);
    cudaGetSymbolAddress((void**)&p_nbrr, g_nbrr);
    cudaGetSymbolAddress((void**)&p_nbrc, g_nbrc);
    cudaGetSymbolAddress((void**)&p_act0, g_act0);
    cudaGetSymbolAddress((void**)&p_act1, g_act1);
    cudaGetSymbolAddress((void**)&p_acnt0, g_acnt0);
    cudaGetSymbolAddress((void**)&p_acnt1, g_acnt1);

    cudaFuncSetAttribute(k_gemm, cudaFuncAttributeMaxDynamicSharedMemorySize, GEMM_SMEM);

    const int G_E    = (EE + TB - 1) / TB;
    const int G_NW   = (NN * 32) / TB;          // 6250  (full gather)
    const int G_NW1  = (K1 * 32) / TB;          // 3125  (act0 gather)
    const int G_NW2  = (K2 * 32 + TB - 1) / TB; // 1563  (act1 gather)
    const int G_GF   = (NN + 63) / 64;          // 782
    const int G_G1   = (K1 + 63) / 64;          // 391
    const int G_G2   = (K2 + 63) / 64;          // 196

    // ---- init + CSR build ----
    k_init<<<256, TB>>>(pvec);
    k_csr_hist<<<G_E, TB>>>(ei);
    k_scan2<<<1, 1024>>>();
    k_csr_fill<<<G_E, TB>>>(ei);

    // ---- down level 0 (dense) ----
    k_gemm<<<G_GF, TB, GEMM_SMEM>>>(x_in, Wd, bd, p_t, nullptr, nullptr, NN);
    k_prep<<<PREP_GRID, TB>>>(p_ecc0, p_ctc0, p_ctr0);
    k_gather_t<false,false,false><<<G_NW, TB>>>(p_t, p_g, p_offc, p_nbrc, p_ecc0,
                                                nullptr, nullptr, 0, nullptr, NN);
    k_gemm<<<G_GF, TB, GEMM_SMEM>>>(p_g, Wd + (size_t)1*DD*DD, bd + 1*DD, p_t,
                                    nullptr, nullptr, NN);
    k_gather_t<false,false,false><<<G_NW, TB>>>(p_t, p_d0, p_offc, p_nbrc, p_ecc0,
                                                nullptr, nullptr, 0, nullptr, NN);
    k_gather_t<false,false,true><<<G_NW, TB>>>(p_d0, p_h, p_offc, p_nbrc, p_ctc0,
                                               nullptr, pvec, 0, nullptr, NN);
    k_topk<<<PREP_GRID, TB>>>(K1, p_act0, p_acnt0);

    // ---- down level 1 (sparse; act0-compacted where legal) ----
    k_gemm<<<G_G1, TB, GEMM_SMEM>>>(p_h, Wd + (size_t)2*DD*DD, bd + 2*DD, p_t,
                                    p_s, p_act0, K1);
    k_prep<<<PREP_GRID, TB>>>(p_ecc1, p_ctc1, p_ctr1);
    k_gather_t<true,false,false><<<G_NW1, TB>>>(p_t, p_g, p_offc, p_nbrc, p_ecc1,
                                                nullptr, nullptr, 0, p_act0, K1);
    k_gemm<<<G_G1, TB, GEMM_SMEM>>>(p_g, Wd + (size_t)3*DD*DD, bd + 3*DD, p_t,
                                    nullptr, p_act0, K1);
    // d1 must be dense-valid (read as dense addin later) -> full gather
    k_gather_t<true,false,false><<<G_NW, TB>>>(p_t, p_d1, p_offc, p_nbrc, p_ecc1,
                                               nullptr, nullptr, 0, nullptr, NN);
    k_gather_t<true,false,true><<<G_NW1, TB>>>(p_d1, p_h, p_offc, p_nbrc, p_ctc1,
                                               nullptr, pvec + DD, 1, p_act0, K1);
    k_topk<<<PREP_GRID, TB>>>(K2, p_act1, p_acnt1);

    // ---- bottom ----
    k_gemm<<<G_G2, TB, GEMM_SMEM>>>(p_h, Wb, bb, p_t, p_s, p_act1, K2);
    k_prep<<<PREP_GRID, TB>>>(p_ecc2, nullptr, nullptr);
    k_gather_t<true,false,false><<<G_NW2, TB>>>(p_t, p_g, p_offc, p_nbrc, p_ecc2,
                                                nullptr, nullptr, 0, p_act1, K2);
    k_gemm<<<G_G2, TB, GEMM_SMEM>>>(p_g, Wb + (size_t)1*DD*DD, bb + 1*DD, p_t,
                                    nullptr, p_act1, K2);
    // x must be valid for all act0 nodes (read by ctr1 gather) -> act0 list
    k_gather_t<true,false,false><<<G_NW1, TB>>>(p_t, p_x, p_offc, p_nbrc, p_ecc2,
                                                nullptr, nullptr, 0, p_act0, K1);

    // ---- up level 0 (act0 domain) ----
    k_gather_t<true,false,false><<<G_NW1, TB>>>(p_x, p_h, p_offr, p_nbrr, p_ctr1,
                                                nullptr, nullptr, 0, p_act0, K1);
    k_gemm<<<G_G1, TB, GEMM_SMEM>>>(p_h, Wu, bu, p_t, nullptr, p_act0, K1);
    k_gather_t<true,false,false><<<G_NW1, TB>>>(p_t, p_g, p_offc, p_nbrc, p_ecc1,
                                                nullptr, nullptr, 0, p_act0, K1);
    k_gemm<<<G_G1, TB, GEMM_SMEM>>>(p_g, Wu + (size_t)1*DD*DD, bu + 1*DD, p_t,
                                    nullptr, p_act0, K1);
    // x = gather + d1 must be dense-valid (read by dense ctr0 gather) -> full
    k_gather_t<true,true,false><<<G_NW, TB>>>(p_t, p_x, p_offc, p_nbrc, p_ecc1,
                                              p_d1, nullptr, 0, nullptr, NN);

    // ---- up level 1 (dense, full graph) ----
    k_gather_t<false,false,false><<<G_NW, TB>>>(p_x, p_h, p_offr, p_nbrr, p_ctr0,
                                                nullptr, nullptr, 0, nullptr, NN);
    k_gemm<<<G_GF, TB, GEMM_SMEM>>>(p_h, Wu + (size_t)2*DD*DD, bu + 2*DD, p_t,
                                    nullptr, nullptr, NN);
    k_gather_t<false,false,false><<<G_NW, TB>>>(p_t, p_g, p_offc, p_nbrc, p_ecc0,
                                                nullptr, nullptr, 0, nullptr, NN);
    k_gemm<<<G_GF, TB, GEMM_SMEM>>>(p_g, Wu + (size_t)3*DD*DD, bu + 3*DD, p_t,
                                    nullptr, nullptr, NN);
    k_gather_t<false,true,false><<<G_NW, TB>>>(p_t, out, p_offc, p_nbrc, p_ecc0,
                                               p_d0, nullptr, 0, nullptr, NN);
}

// round 6
// speedup vs baseline: 1.0565x; 1.0565x over previous
#include <cuda_runtime.h>
#include <cstdint>

// Problem constants
#define NN 50000
#define DD 128
#define EE 800000
#define ND (NN*DD)
#define TB 256
#define K1 25000
#define K2 12500
#define PREP_GRID 196            // ceil(NN/256)
#define GSTRIDE (PREP_GRID*TB)   // 50176

// ----------------------------------------------------------------------------
// Device scratch (allocation-free: __device__ globals)
// ----------------------------------------------------------------------------
__device__ float g_h[ND];
__device__ float g_t[ND];
__device__ float g_g[ND];
__device__ float g_xx[ND];
__device__ float g_d0[ND];
__device__ float g_d1[ND];
__device__ int   g_nbrr[EE];
__device__ int   g_nbrc[EE];
__device__ float g_ecc0[EE];
__device__ float g_ecc1[EE];
__device__ float g_ecc2[EE];
__device__ float g_ctc0[EE];
__device__ float g_ctc1[EE];
__device__ float g_ctr0[EE];
__device__ float g_ctr1[EE];
__device__ float g_dis[NN];
__device__ float g_normed[NN];
__device__ float g_aggr[NN];
__device__ float g_w[NN];
__device__ float g_nm[NN];
__device__ float g_score[NN];
__device__ float g_s[NN];
__device__ unsigned long long g_key[NN];
__device__ unsigned int g_hist[65536];
__device__ unsigned long long g_prefix;
__device__ int g_k;
__device__ float g_pinv[2];
__device__ int g_cntr[NN];
__device__ int g_cntc[NN];
__device__ int g_offr[NN + 1];
__device__ int g_offc[NN + 1];
__device__ int g_curr[NN];
__device__ int g_curc[NN];
__device__ int g_act0[NN];
__device__ int g_act1[NN];
__device__ int g_acnt0;
__device__ int g_acnt1;
// software grid barrier — self-cleaning across graph replays (barcnt returns to
// 0 after each release; bargen only ever increments, replay-safe). NEVER reset.
__device__ int g_barcnt = 0;
__device__ unsigned g_bargen = 0u;

// ----------------------------------------------------------------------------
// f32x2 packed-FMA helpers
// ----------------------------------------------------------------------------
__device__ __forceinline__ unsigned long long fma2(unsigned long long a,
                                                   unsigned long long b,
                                                   unsigned long long c) {
    unsigned long long d;
    asm("fma.rn.f32x2 %0, %1, %2, %3;" : "=l"(d) : "l"(a), "l"(b), "l"(c));
    return d;
}
__device__ __forceinline__ unsigned long long pack2(float x) {
    unsigned long long d;
    asm("mov.b64 %0, {%1, %1};" : "=l"(d) : "f"(x));
    return d;
}
__device__ __forceinline__ float2 unpack2(unsigned long long v) {
    float2 r;
    asm("mov.b64 {%0, %1}, %2;" : "=f"(r.x), "=f"(r.y) : "l"(v));
    return r;
}

// ----------------------------------------------------------------------------
// Software grid barrier (all blocks co-resident; grids <= PREP_GRID blocks)
// ----------------------------------------------------------------------------
__device__ __forceinline__ void gridbar() {
    __syncthreads();
    if (threadIdx.x == 0) {
        unsigned gen = *((volatile unsigned*)&g_bargen);
        __threadfence();
        int ticket = atomicAdd(&g_barcnt, 1);
        if (ticket == (int)gridDim.x - 1) {
            g_barcnt = 0;
            __threadfence();
            atomicAdd(&g_bargen, 1u);
        } else {
            while (*((volatile unsigned*)&g_bargen) == gen) {}
        }
        __threadfence();
    }
    __syncthreads();
}

// ----------------------------------------------------------------------------
// Launch #1: init (hist zero, nm/w/cnt, pinv, acnt) -> [bar] -> edge histogram
// ----------------------------------------------------------------------------
__global__ void __launch_bounds__(TB) k_init_hist(const float* __restrict__ pvec,
                                                  const int* __restrict__ ei) {
    int gid = blockIdx.x * blockDim.x + threadIdx.x;
    for (int j = gid; j < 65536; j += GSTRIDE) g_hist[j] = 0u;
    if (gid < NN) { g_nm[gid] = 1.0f; g_w[gid] = 1.0f; g_cntr[gid] = 0; g_cntc[gid] = 0; }
    if (gid == 0) { g_acnt0 = 0; g_acnt1 = 0; }
    if (blockIdx.x == 0 && threadIdx.x < 64) {
        int l = threadIdx.x >> 5, lane = threadIdx.x & 31;
        float4 p = ((const float4*)(pvec + l * DD))[lane];
        float s = p.x*p.x + p.y*p.y + p.z*p.z + p.w*p.w;
        #pragma unroll
        for (int o = 16; o; o >>= 1) s += __shfl_xor_sync(0xffffffffu, s, o);
        if (lane == 0) g_pinv[l] = rsqrtf(s);
    }
    gridbar();
    for (int e = gid; e < EE; e += GSTRIDE) {
        atomicAdd(&g_cntr[ei[e]], 1);
        atomicAdd(&g_cntc[ei[EE + e]], 1);
    }
}

// ----------------------------------------------------------------------------
// Launch #3: scans (block 0) -> [bar] -> csr fill -> [bar] -> level-0 prep
// ----------------------------------------------------------------------------
__device__ void scan256(const int* __restrict__ cnt, int* __restrict__ off,
                        int* __restrict__ cur, int* part) {
    const int PER = 196;   // 256*196 = 50176 >= NN
    int t = threadIdx.x;
    int base = t * PER;
    int s = 0;
    for (int i = 0; i < PER; i++) { int idx = base + i; if (idx < NN) s += cnt[idx]; }
    part[t] = s;
    __syncthreads();
    if (t == 0) {
        int acc = 0;
        for (int i = 0; i < 256; i++) { int v = part[i]; part[i] = acc; acc += v; }
        off[NN] = acc;
    }
    __syncthreads();
    int run = part[t];
    for (int i = 0; i < PER; i++) {
        int idx = base + i;
        if (idx < NN) { off[idx] = run; cur[idx] = run; run += cnt[idx]; }
    }
}

__global__ void __launch_bounds__(TB) k_sfp(const int* __restrict__ ei,
                                            float* __restrict__ ecc,
                                            float* __restrict__ ctc,
                                            float* __restrict__ ctr) {
    __shared__ int part[256];
    int gid = blockIdx.x * blockDim.x + threadIdx.x;
    if (blockIdx.x == 0) {
        scan256(g_cntr, g_offr, g_curr, part);
        __syncthreads();
        scan256(g_cntc, g_offc, g_curc, part);
    }
    gridbar();
    // csr fill (grid-stride over E)
    for (int e = gid; e < EE; e += GSTRIDE) {
        int r = ei[e], c = ei[EE + e];
        int pr = atomicAdd(&g_curr[r], 1);
        g_nbrr[pr] = c;
        int pc = atomicAdd(&g_curc[c], 1);
        g_nbrc[pc] = r;
    }
    gridbar();
    // level-0 prep: all masks are 1, so deg = row-degree, etc.
    int v = gid;
    if (v < NN) {
        int s = g_offr[v], e = g_offr[v + 1];
        float sum = 0.f;
        for (int i = s; i < e; i++) sum += g_nm[g_nbrr[i]];
        float d = g_nm[v] * sum;
        float dis_, nrm;
        if (d > 0.f) { dis_ = rsqrtf(d); nrm = g_w[v] / d; }
        else         { dis_ = 0.f; nrm = 0.f; }
        g_dis[v] = dis_;
        g_normed[v] = nrm;
    }
    gridbar();
    if (v < NN) {
        int c = v;
        int s = g_offc[c], e = g_offc[c + 1];
        float nmc = g_nm[c], disc = g_dis[c];
        float ag = 0.f;
        for (int i = s; i < e; i++) {
            int r = g_nbrc[i];
            ag = fmaf(g_normed[r], g_nm[r], ag);
        }
        float aggr = fmaf(nmc, ag, 1e-12f);
        g_aggr[c] = aggr;
        float inv = nmc / aggr;
        for (int i = s; i < e; i++) {
            int r = g_nbrc[i];
            ecc[i] = g_dis[r] * disc;
            ctc[i] = g_normed[r] * g_nm[r] * inv;
        }
    }
    gridbar();
    if (v < NN) {
        int r = v;
        int s = g_offr[r], e = g_offr[r + 1];
        float base = g_normed[r] * g_nm[r];
        for (int i = s; i < e; i++) {
            int c = g_nbrr[i];
            ctr[i] = base * g_nm[c] / g_aggr[c];
        }
    }
}

// ----------------------------------------------------------------------------
// Per-level prep for levels 1,2 (3-phase grid-barrier kernel, from R5)
// ----------------------------------------------------------------------------
__global__ void __launch_bounds__(TB) k_prep(float* __restrict__ ecc,
                                             float* __restrict__ ctc,
                                             float* __restrict__ ctr) {
    int v = blockIdx.x * blockDim.x + threadIdx.x;
    if (v < NN) {
        int s = g_offr[v], e = g_offr[v + 1];
        float sum = 0.f;
        for (int i = s; i < e; i++) sum += g_nm[g_nbrr[i]];
        float d = g_nm[v] * sum;
        float dis_, nrm;
        if (d > 0.f) { dis_ = rsqrtf(d); nrm = g_w[v] / d; }
        else         { dis_ = 0.f; nrm = 0.f; }
        g_dis[v] = dis_;
        g_normed[v] = nrm;
    }
    gridbar();
    if (v < NN) {
        int c = v;
        int s = g_offc[c], e = g_offc[c + 1];
        float nmc = g_nm[c], disc = g_dis[c];
        float ag = 0.f;
        for (int i = s; i < e; i++) {
            int r = g_nbrc[i];
            ag = fmaf(g_normed[r], g_nm[r], ag);
        }
        float aggr = fmaf(nmc, ag, 1e-12f);
        g_aggr[c] = aggr;
        float inv = nmc / aggr;
        for (int i = s; i < e; i++) {
            int r = g_nbrc[i];
            ecc[i] = g_dis[r] * disc;
            if (ctc) ctc[i] = g_normed[r] * g_nm[r] * inv;
        }
    }
    if (!ctr) return;
    gridbar();
    if (v < NN) {
        int r = v;
        int s = g_offr[r], e = g_offr[r + 1];
        float base = g_normed[r] * g_nm[r];
        for (int i = s; i < e; i++) {
            int c = g_nbrr[i];
            ctr[i] = base * g_nm[c] / g_aggr[c];
        }
    }
}

// ----------------------------------------------------------------------------
// CSR pull-gather (warp per node, float4 per lane); optional node list.
// ----------------------------------------------------------------------------
template<bool SKIP, bool ADDIN, bool SCORE>
__global__ void __launch_bounds__(256) k_gather_t(
    const float* __restrict__ src, float* __restrict__ dst,
    const int* __restrict__ off, const int* __restrict__ nbr,
    const float* __restrict__ cf, const float* __restrict__ addin,
    const float* __restrict__ pv, int lvl,
    const int* __restrict__ list, int nlist) {
    int wid = (blockIdx.x * blockDim.x + threadIdx.x) >> 5;
    if (wid >= nlist) return;
    int v = list ? list[wid] : wid;
    int lane = threadIdx.x & 31;
    int s = off[v], e = off[v + 1];
    float ax = 0.f, ay = 0.f, az = 0.f, aw = 0.f;
    int i = s;
    if (!SKIP) {
        int e8 = s + ((e - s) & ~7);
        for (; i < e8; i += 8) {
            int n[8]; float w[8]; float4 t[8];
            #pragma unroll
            for (int u = 0; u < 8; u++) { n[u] = nbr[i + u]; w[u] = cf[i + u]; }
            #pragma unroll
            for (int u = 0; u < 8; u++)
                t[u] = ((const float4*)src)[(size_t)n[u] * 32 + lane];
            #pragma unroll
            for (int u = 0; u < 8; u++) {
                ax = fmaf(w[u], t[u].x, ax); ay = fmaf(w[u], t[u].y, ay);
                az = fmaf(w[u], t[u].z, az); aw = fmaf(w[u], t[u].w, aw);
            }
        }
    } else {
        for (; i + 4 <= e; i += 4) {
            int   n0 = nbr[i],   n1 = nbr[i+1],   n2 = nbr[i+2],   n3 = nbr[i+3];
            float w0 = cf[i],    w1 = cf[i+1],    w2 = cf[i+2],    w3 = cf[i+3];
            if (w0 != 0.f) {
                float4 t = ((const float4*)src)[(size_t)n0 * 32 + lane];
                ax = fmaf(w0, t.x, ax); ay = fmaf(w0, t.y, ay);
                az = fmaf(w0, t.z, az); aw = fmaf(w0, t.w, aw);
            }
            if (w1 != 0.f) {
                float4 t = ((const float4*)src)[(size_t)n1 * 32 + lane];
                ax = fmaf(w1, t.x, ax); ay = fmaf(w1, t.y, ay);
                az = fmaf(w1, t.z, az); aw = fmaf(w1, t.w, aw);
            }
            if (w2 != 0.f) {
                float4 t = ((const float4*)src)[(size_t)n2 * 32 + lane];
                ax = fmaf(w2, t.x, ax); ay = fmaf(w2, t.y, ay);
                az = fmaf(w2, t.z, az); aw = fmaf(w2, t.w, aw);
            }
            if (w3 != 0.f) {
                float4 t = ((const float4*)src)[(size_t)n3 * 32 + lane];
                ax = fmaf(w3, t.x, ax); ay = fmaf(w3, t.y, ay);
                az = fmaf(w3, t.z, az); aw = fmaf(w3, t.w, aw);
            }
        }
    }
    for (; i < e; i++) {
        int n = nbr[i]; float w = cf[i];
        if (!SKIP || w != 0.f) {
            float4 t = ((const float4*)src)[(size_t)n * 32 + lane];
            ax = fmaf(w, t.x, ax); ay = fmaf(w, t.y, ay);
            az = fmaf(w, t.z, az); aw = fmaf(w, t.w, aw);
        }
    }
    if (ADDIN) {
        float4 a = ((const float4*)addin)[(size_t)v * 32 + lane];
        ax += a.x; ay += a.y; az += a.z; aw += a.w;
    }
    ((float4*)dst)[(size_t)v * 32 + lane] = make_float4(ax, ay, az, aw);
    if (SCORE) {
        float4 p = ((const float4*)pv)[lane];
        float sdot = ax*p.x + ay*p.y + az*p.z + aw*p.w;
        #pragma unroll
        for (int o = 16; o; o >>= 1) sdot += __shfl_xor_sync(0xffffffffu, sdot, o);
        if (lane == 0) g_score[v] = sdot * g_pinv[lvl];
    }
}

// ----------------------------------------------------------------------------
// Dense GEMM (R4 version): 128-row tile, 256 threads, 8x8/thread, FFMA2
// ----------------------------------------------------------------------------
#define GEMM_SMEM ((128*128 + 128*132) * 4)
__global__ void __launch_bounds__(256) k_gemm(const float* __restrict__ A,
                                              const float* __restrict__ W,
                                              const float* __restrict__ bias,
                                              float* __restrict__ C,
                                              const float* __restrict__ scale,
                                              const int* __restrict__ rowidx,
                                              int m) {
    extern __shared__ float sm[];
    float* sW = sm;              // [128][128]
    float* sA = sm + 128 * 128;  // [128][132] padded
    const int tid = threadIdx.x;
    const int row0 = blockIdx.x * 128;

    #pragma unroll 4
    for (int i = tid; i < 128 * 32; i += 256) {
        int r = i >> 5, c = (i & 31) << 2;
        *(float4*)(sW + r * 128 + c) = *(const float4*)(W + r * 128 + c);
    }
    #pragma unroll 4
    for (int i = tid; i < 128 * 32; i += 256) {
        int r = i >> 5, c = (i & 31) << 2;
        int rl = row0 + r;
        float4 v = make_float4(0.f, 0.f, 0.f, 0.f);
        if (rl < m) {
            int row = rowidx ? rowidx[rl] : rl;
            v = *(const float4*)(A + (size_t)row * DD + c);
            if (scale) {
                float sc = scale[row];
                v.x *= sc; v.y *= sc; v.z *= sc; v.w *= sc;
            }
        }
        *(float4*)(sA + r * 132 + c) = v;
    }
    __syncthreads();

    const int tx = tid & 15, ty = tid >> 4;
    const int rb = ty * 8, cb = tx * 8;
    unsigned long long acc[8][4] = {};

    #pragma unroll 4
    for (int k = 0; k < 128; k++) {
        ulonglong2 w0 = *(ulonglong2*)(sW + k * 128 + cb);
        ulonglong2 w1 = *(ulonglong2*)(sW + k * 128 + cb + 4);
        #pragma unroll
        for (int r = 0; r < 8; r++) {
            unsigned long long aa = pack2(sA[(rb + r) * 132 + k]);
            acc[r][0] = fma2(aa, w0.x, acc[r][0]);
            acc[r][1] = fma2(aa, w0.y, acc[r][1]);
            acc[r][2] = fma2(aa, w1.x, acc[r][2]);
            acc[r][3] = fma2(aa, w1.y, acc[r][3]);
        }
    }

    float4 b0 = *(const float4*)(bias + cb);
    float4 b1 = *(const float4*)(bias + cb + 4);
    #pragma unroll
    for (int r = 0; r < 8; r++) {
        int rl = row0 + rb + r;
        if (rl < m) {
            int row = rowidx ? rowidx[rl] : rl;
            float2 p0 = unpack2(acc[r][0]);
            float2 p1 = unpack2(acc[r][1]);
            float2 p2 = unpack2(acc[r][2]);
            float2 p3 = unpack2(acc[r][3]);
            float4 o0 = make_float4(p0.x + b0.x, p0.y + b0.y, p1.x + b0.z, p1.y + b0.w);
            float4 o1 = make_float4(p2.x + b1.x, p2.y + b1.y, p3.x + b1.z, p3.y + b1.w);
            *(float4*)(C + (size_t)row * DD + cb)     = o0;
            *(float4*)(C + (size_t)row * DD + cb + 4) = o1;
        }
    }
}

// ----------------------------------------------------------------------------
// TopK (R4 version): keys, 4x(count, parallel scan), apply+compact
// ----------------------------------------------------------------------------
__global__ void k_keys(int kval) {
    int v = blockIdx.x * blockDim.x + threadIdx.x;
    if (v == 0) { g_prefix = 0ull; g_k = kval; }
    if (v >= NN) return;
    float s = (g_nm[v] > 0.f) ? g_score[v] : __int_as_float(0xff800000);
    unsigned u = __float_as_uint(s);
    u = (u & 0x80000000u) ? ~u : (u | 0x80000000u);
    g_key[v] = ((unsigned long long)u << 32) | (unsigned long long)(0xFFFFFFFFu - (unsigned)v);
}

__global__ void k_count(int pass) {
    int v = blockIdx.x * blockDim.x + threadIdx.x;
    if (v >= NN) return;
    unsigned long long key = g_key[v];
    if (pass) {
        if ((key >> (64 - 16 * pass)) != g_prefix) return;
    }
    unsigned d = (unsigned)(key >> (48 - 16 * pass)) & 0xFFFFu;
    atomicAdd(&g_hist[d], 1u);
}

__global__ void k_scan() {
    __shared__ unsigned int sf[1024];
    int t = threadIdx.x;
    unsigned int s = 0;
    #pragma unroll 8
    for (int b = 0; b < 64; b++) s += g_hist[t * 64 + b];
    sf[t] = s;
    __syncthreads();
    for (int off = 1; off < 1024; off <<= 1) {
        unsigned int v = sf[t];
        unsigned int add = (t + off < 1024) ? sf[t + off] : 0u;
        __syncthreads();
        sf[t] = v + add;
        __syncthreads();
    }
    unsigned int k = (unsigned int)g_k;
    unsigned int above = (t < 1023) ? sf[t + 1] : 0u;
    if (above < k && sf[t] >= k) {
        unsigned int cum = above;
        int d = 0;
        for (int b = 63; b >= 0; b--) {
            unsigned int h = g_hist[t * 64 + b];
            if (cum + h >= k) { d = t * 64 + b; break; }
            cum += h;
        }
        g_prefix = (g_prefix << 16) | (unsigned long long)(unsigned)d;
        g_k = (int)(k - cum);
    }
    __syncthreads();
    #pragma unroll 8
    for (int b = 0; b < 64; b++) g_hist[t * 64 + b] = 0u;
}

__global__ void k_applynode(int* __restrict__ act, int* __restrict__ acnt) {
    int v = blockIdx.x * blockDim.x + threadIdx.x;
    if (v >= NN) return;
    bool kept = (g_key[v] >= g_prefix);
    g_nm[v] = kept ? 1.f : 0.f;
    g_w[v]  = kept ? g_aggr[v] : 0.f;
    g_s[v]  = kept ? tanhf(g_score[v]) : 0.f;
    if (kept) {
        int slot = atomicAdd(acnt, 1);
        act[slot] = v;
    }
}

// ----------------------------------------------------------------------------
// Host orchestration
// ----------------------------------------------------------------------------
extern "C" void kernel_launch(void* const* d_in, const int* in_sizes, int n_in,
                              void* d_out, int out_size) {
    const float* x_in = (const float*)d_in[0];
    const int*   ei   = (const int*)d_in[1];
    const float* Wd   = (const float*)d_in[2];
    const float* bd   = (const float*)d_in[3];
    const float* Wu   = (const float*)d_in[4];
    const float* bu   = (const float*)d_in[5];
    const float* Wb   = (const float*)d_in[6];
    const float* bb   = (const float*)d_in[7];
    const float* pvec = (const float*)d_in[8];
    float* out = (float*)d_out;

    float *p_h, *p_t, *p_g, *p_x, *p_d0, *p_d1;
    float *p_ecc0, *p_ecc1, *p_ecc2, *p_ctc0, *p_ctc1, *p_ctr0, *p_ctr1, *p_s;
    int *p_offr, *p_offc, *p_nbrr, *p_nbrc, *p_act0, *p_act1, *p_acnt0, *p_acnt1;
    cudaGetSymbolAddress((void**)&p_h, g_h);
    cudaGetSymbolAddress((void**)&p_t, g_t);
    cudaGetSymbolAddress((void**)&p_g, g_g);
    cudaGetSymbolAddress((void**)&p_x, g_xx);
    cudaGetSymbolAddress((void**)&p_d0, g_d0);
    cudaGetSymbolAddress((void**)&p_d1, g_d1);
    cudaGetSymbolAddress((void**)&p_ecc0, g_ecc0);
    cudaGetSymbolAddress((void**)&p_ecc1, g_ecc1);
    cudaGetSymbolAddress((void**)&p_ecc2, g_ecc2);
    cudaGetSymbolAddress((void**)&p_ctc0, g_ctc0);
    cudaGetSymbolAddress((void**)&p_ctc1, g_ctc1);
    cudaGetSymbolAddress((void**)&p_ctr0, g_ctr0);
    cudaGetSymbolAddress((void**)&p_ctr1, g_ctr1);
    cudaGetSymbolAddress((void**)&p_s, g_s);
    cudaGetSymbolAddress((void**)&p_offr, g_offr);
    cudaGetSymbolAddress((void**)&p_offc, g_offc);
    cudaGetSymbolAddress((void**)&p_nbrr, g_nbrr);
    cudaGetSymbolAddress((void**)&p_nbrc, g_nbrc);
    cudaGetSymbolAddress((void**)&p_act0, g_act0);
    cudaGetSymbolAddress((void**)&p_act1, g_act1);
    cudaGetSymbolAddress((void**)&p_acnt0, g_acnt0);
    cudaGetSymbolAddress((void**)&p_acnt1, g_acnt1);

    cudaFuncSetAttribute(k_gemm, cudaFuncAttributeMaxDynamicSharedMemorySize, GEMM_SMEM);

    const int G_N    = (NN + TB - 1) / TB;      // 196
    const int G_NW   = (NN * 32) / TB;          // 6250  (full gather)
    const int G_NW1  = (K1 * 32) / TB;          // 3125  (act0 gather)
    const int G_NW2  = (K2 * 32 + TB - 1) / TB; // 1563  (act1 gather)
    const int G_GF   = (NN + 127) / 128;        // 391
    const int G_G1   = (K1 + 127) / 128;        // 196
    const int G_G2   = (K2 + 127) / 128;        // 98

    // ---- prefix: init+hist(1), gemm(2), scan+fill+prep0(3), dense gather(4) ----
    k_init_hist<<<PREP_GRID, TB>>>(pvec, ei);                               // #1
    k_gemm<<<G_GF, TB, GEMM_SMEM>>>(x_in, Wd, bd, p_t, nullptr, nullptr, NN); // #2
    k_sfp<<<PREP_GRID, TB>>>(ei, p_ecc0, p_ctc0, p_ctr0);                   // #3
    k_gather_t<false,false,false><<<G_NW, TB>>>(p_t, p_g, p_offc, p_nbrc, p_ecc0,
                                                nullptr, nullptr, 0, nullptr, NN); // #4 (profiled)

    // ---- down level 0 (dense, continued) ----
    k_gemm<<<G_GF, TB, GEMM_SMEM>>>(p_g, Wd + (size_t)1*DD*DD, bd + 1*DD, p_t,
                                    nullptr, nullptr, NN);
    k_gather_t<false,false,false><<<G_NW, TB>>>(p_t, p_d0, p_offc, p_nbrc, p_ecc0,
                                                nullptr, nullptr, 0, nullptr, NN);
    k_gather_t<false,false,true><<<G_NW, TB>>>(p_d0, p_h, p_offc, p_nbrc, p_ctc0,
                                               nullptr, pvec, 0, nullptr, NN);
    k_keys<<<G_N, TB>>>(K1);
    for (int p = 0; p < 4; p++) { k_count<<<G_N, TB>>>(p); k_scan<<<1, 1024>>>(); }
    k_applynode<<<G_N, TB>>>(p_act0, p_acnt0);

    // ---- down level 1 (sparse; act0-compacted where legal) ----
    k_gemm<<<G_G1, TB, GEMM_SMEM>>>(p_h, Wd + (size_t)2*DD*DD, bd + 2*DD, p_t,
                                    p_s, p_act0, K1);
    k_prep<<<PREP_GRID, TB>>>(p_ecc1, p_ctc1, p_ctr1);
    k_gather_t<true,false,false><<<G_NW1, TB>>>(p_t, p_g, p_offc, p_nbrc, p_ecc1,
                                                nullptr, nullptr, 0, p_act0, K1);
    k_gemm<<<G_G1, TB, GEMM_SMEM>>>(p_g, Wd + (size_t)3*DD*DD, bd + 3*DD, p_t,
                                    nullptr, p_act0, K1);
    // d1 must be dense-valid (read as dense addin later) -> full gather
    k_gather_t<true,false,false><<<G_NW, TB>>>(p_t, p_d1, p_offc, p_nbrc, p_ecc1,
                                               nullptr, nullptr, 0, nullptr, NN);
    k_gather_t<true,false,true><<<G_NW1, TB>>>(p_d1, p_h, p_offc, p_nbrc, p_ctc1,
                                               nullptr, pvec + DD, 1, p_act0, K1);
    k_keys<<<G_N, TB>>>(K2);
    for (int p = 0; p < 4; p++) { k_count<<<G_N, TB>>>(p); k_scan<<<1, 1024>>>(); }
    k_applynode<<<G_N, TB>>>(p_act1, p_acnt1);

    // ---- bottom ----
    k_gemm<<<G_G2, TB, GEMM_SMEM>>>(p_h, Wb, bb, p_t, p_s, p_act1, K2);
    k_prep<<<PREP_GRID, TB>>>(p_ecc2, nullptr, nullptr);
    k_gather_t<true,false,false><<<G_NW2, TB>>>(p_t, p_g, p_offc, p_nbrc, p_ecc2,
                                                nullptr, nullptr, 0, p_act1, K2);
    k_gemm<<<G_G2, TB, GEMM_SMEM>>>(p_g, Wb + (size_t)1*DD*DD, bb + 1*DD, p_t,
                                    nullptr, p_act1, K2);
    // x must be valid for all act0 nodes (read by ctr1 gather) -> act0 list
    k_gather_t<true,false,false><<<G_NW1, TB>>>(p_t, p_x, p_offc, p_nbrc, p_ecc2,
                                                nullptr, nullptr, 0, p_act0, K1);

    // ---- up level 0 (act0 domain) ----
    k_gather_t<true,false,false><<<G_NW1, TB>>>(p_x, p_h, p_offr, p_nbrr, p_ctr1,
                                                nullptr, nullptr, 0, p_act0, K1);
    k_gemm<<<G_G1, TB, GEMM_SMEM>>>(p_h, Wu, bu, p_t, nullptr, p_act0, K1);
    k_gather_t<true,false,false><<<G_NW1, TB>>>(p_t, p_g, p_offc, p_nbrc, p_ecc1,
                                                nullptr, nullptr, 0, p_act0, K1);
    k_gemm<<<G_G1, TB, GEMM_SMEM>>>(p_g, Wu + (size_t)1*DD*DD, bu + 1*DD, p_t,
                                    nullptr, p_act0, K1);
    // x = gather + d1 must be dense-valid (read by dense ctr0 gather) -> full
    k_gather_t<true,true,false><<<G_NW, TB>>>(p_t, p_x, p_offc, p_nbrc, p_ecc1,
                                              p_d1, nullptr, 0, nullptr, NN);

    // ---- up level 1 (dense, full graph) ----
    k_gather_t<false,false,false><<<G_NW, TB>>>(p_x, p_h, p_offr, p_nbrr, p_ctr0,
                                                nullptr, nullptr, 0, nullptr, NN);
    k_gemm<<<G_GF, TB, GEMM_SMEM>>>(p_h, Wu + (size_t)2*DD*DD, bu + 2*DD, p_t,
                                    nullptr, nullptr, NN);
    k_gather_t<false,false,false><<<G_NW, TB>>>(p_t, p_g, p_offc, p_nbrc, p_ecc0,
                                                nullptr, nullptr, 0, nullptr, NN);
    k_gemm<<<G_GF, TB, GEMM_SMEM>>>(p_g, Wu + (size_t)3*DD*DD, bu + 3*DD, p_t,
                                    nullptr, nullptr, NN);
    k_gather_t<false,true,false><<<G_NW, TB>>>(p_t, out, p_offc, p_nbrc, p_ecc0,
                                               p_d0, nullptr, 0, nullptr, NN);
}

// round 9
// speedup vs baseline: 1.0658x; 1.0088x over previous
#include <cuda_runtime.h>
#include <cstdint>

// Problem constants
#define NN 50000
#define DD 128
#define EE 800000
#define ND (NN*DD)
#define TB 256
#define K1 25000
#define K2 12500
#define PREP_GRID 196            // ceil(NN/256)
#define GSTRIDE (PREP_GRID*TB)   // 50176

// ----------------------------------------------------------------------------
// Device scratch (allocation-free: __device__ globals)
// ----------------------------------------------------------------------------
__device__ float g_h[ND];
__device__ float g_t[ND];
__device__ float g_g[ND];
__device__ float g_xx[ND];
__device__ float g_d0[ND];
__device__ float g_d1[ND];
__device__ int   g_nbrr[EE];
__device__ int   g_nbrc[EE];
__device__ float g_ecc0[EE];
__device__ float g_ecc1[EE];
__device__ float g_ecc2[EE];
__device__ float g_ctc0[EE];
__device__ float g_ctc1[EE];
__device__ float g_ctr0[EE];
__device__ float g_ctr1[EE];
__device__ float g_dis[NN];
__device__ float g_normed[NN];
__device__ float g_aggr[NN];
__device__ float g_w[NN];
__device__ float g_nm[NN];
__device__ float g_score[NN];
__device__ float g_s[NN];
__device__ unsigned long long g_key[NN];
__device__ unsigned int g_hist[65536];
__device__ unsigned long long g_prefix;
__device__ int g_k;
__device__ float g_pinv[2];
__device__ int g_cntr[NN];
__device__ int g_cntc[NN];
__device__ int g_offr[NN + 1];
__device__ int g_offc[NN + 1];
__device__ int g_curr[NN];
__device__ int g_curc[NN];
__device__ int g_act0[NN];
__device__ int g_act1[NN];
__device__ int g_acnt0;
__device__ int g_acnt1;
// software grid barrier — self-cleaning across graph replays; NEVER reset.
__device__ int g_barcnt = 0;
__device__ unsigned g_bargen = 0u;

// ----------------------------------------------------------------------------
// f32x2 packed-FMA helpers
// ----------------------------------------------------------------------------
__device__ __forceinline__ unsigned long long fma2(unsigned long long a,
                                                   unsigned long long b,
                                                   unsigned long long c) {
    unsigned long long d;
    asm("fma.rn.f32x2 %0, %1, %2, %3;" : "=l"(d) : "l"(a), "l"(b), "l"(c));
    return d;
}
__device__ __forceinline__ unsigned long long pack2(float x) {
    unsigned long long d;
    asm("mov.b64 %0, {%1, %1};" : "=l"(d) : "f"(x));
    return d;
}
__device__ __forceinline__ float2 unpack2(unsigned long long v) {
    float2 r;
    asm("mov.b64 {%0, %1}, %2;" : "=f"(r.x), "=f"(r.y) : "l"(v));
    return r;
}

// ----------------------------------------------------------------------------
// Software grid barrier (all blocks co-resident; grids <= PREP_GRID blocks)
// ----------------------------------------------------------------------------
__device__ __forceinline__ void gridbar() {
    __syncthreads();
    if (threadIdx.x == 0) {
        unsigned gen = *((volatile unsigned*)&g_bargen);
        __threadfence();
        int ticket = atomicAdd(&g_barcnt, 1);
        if (ticket == (int)gridDim.x - 1) {
            g_barcnt = 0;
            __threadfence();
            atomicAdd(&g_bargen, 1u);
        } else {
            while (*((volatile unsigned*)&g_bargen) == gen) {}
        }
        __threadfence();
    }
    __syncthreads();
}

// ----------------------------------------------------------------------------
// Launch #1: init -> [bar] -> edge histogram
// ----------------------------------------------------------------------------
__global__ void __launch_bounds__(TB) k_init_hist(const float* __restrict__ pvec,
                                                  const int* __restrict__ ei) {
    int gid = blockIdx.x * blockDim.x + threadIdx.x;
    for (int j = gid; j < 65536; j += GSTRIDE) g_hist[j] = 0u;
    if (gid < NN) { g_nm[gid] = 1.0f; g_w[gid] = 1.0f; g_cntr[gid] = 0; g_cntc[gid] = 0; }
    if (gid == 0) { g_acnt0 = 0; g_acnt1 = 0; }
    if (blockIdx.x == 0 && threadIdx.x < 64) {
        int l = threadIdx.x >> 5, lane = threadIdx.x & 31;
        float4 p = ((const float4*)(pvec + l * DD))[lane];
        float s = p.x*p.x + p.y*p.y + p.z*p.z + p.w*p.w;
        #pragma unroll
        for (int o = 16; o; o >>= 1) s += __shfl_xor_sync(0xffffffffu, s, o);
        if (lane == 0) g_pinv[l] = rsqrtf(s);
    }
    gridbar();
    for (int e = gid; e < EE; e += GSTRIDE) {
        atomicAdd(&g_cntr[ei[e]], 1);
        atomicAdd(&g_cntc[ei[EE + e]], 1);
    }
}

// ----------------------------------------------------------------------------
// Launch #3: scans (block 0) -> [bar] -> csr fill -> [bar] -> level-0 prep
// ----------------------------------------------------------------------------
__device__ void scan256(const int* __restrict__ cnt, int* __restrict__ off,
                        int* __restrict__ cur, int* part) {
    const int PER = 196;   // 256*196 = 50176 >= NN
    int t = threadIdx.x;
    int base = t * PER;
    int s = 0;
    for (int i = 0; i < PER; i++) { int idx = base + i; if (idx < NN) s += cnt[idx]; }
    part[t] = s;
    __syncthreads();
    if (t == 0) {
        int acc = 0;
        for (int i = 0; i < 256; i++) { int v = part[i]; part[i] = acc; acc += v; }
        off[NN] = acc;
    }
    __syncthreads();
    int run = part[t];
    for (int i = 0; i < PER; i++) {
        int idx = base + i;
        if (idx < NN) { off[idx] = run; cur[idx] = run; run += cnt[idx]; }
    }
}

__global__ void __launch_bounds__(TB) k_sfp(const int* __restrict__ ei,
                                            float* __restrict__ ecc,
                                            float* __restrict__ ctc,
                                            float* __restrict__ ctr) {
    __shared__ int part[256];
    int gid = blockIdx.x * blockDim.x + threadIdx.x;
    if (blockIdx.x == 0) {
        scan256(g_cntr, g_offr, g_curr, part);
        __syncthreads();
        scan256(g_cntc, g_offc, g_curc, part);
    }
    gridbar();
    // csr fill (grid-stride over E)
    for (int e = gid; e < EE; e += GSTRIDE) {
        int r = ei[e], c = ei[EE + e];
        int pr = atomicAdd(&g_curr[r], 1);
        g_nbrr[pr] = c;
        int pc = atomicAdd(&g_curc[c], 1);
        g_nbrc[pc] = r;
    }
    gridbar();
    // level-0 prep
    int v = gid;
    if (v < NN) {
        int s = g_offr[v], e = g_offr[v + 1];
        float sum = 0.f;
        for (int i = s; i < e; i++) sum += g_nm[g_nbrr[i]];
        float d = g_nm[v] * sum;
        float dis_, nrm;
        if (d > 0.f) { dis_ = rsqrtf(d); nrm = g_w[v] / d; }
        else         { dis_ = 0.f; nrm = 0.f; }
        g_dis[v] = dis_;
        g_normed[v] = nrm;
    }
    gridbar();
    if (v < NN) {
        int c = v;
        int s = g_offc[c], e = g_offc[c + 1];
        float nmc = g_nm[c], disc = g_dis[c];
        float ag = 0.f;
        for (int i = s; i < e; i++) {
            int r = g_nbrc[i];
            ag = fmaf(g_normed[r], g_nm[r], ag);
        }
        float aggr = fmaf(nmc, ag, 1e-12f);
        g_aggr[c] = aggr;
        float inv = nmc / aggr;
        for (int i = s; i < e; i++) {
            int r = g_nbrc[i];
            ecc[i] = g_dis[r] * disc;
            ctc[i] = g_normed[r] * g_nm[r] * inv;
        }
    }
    gridbar();
    if (v < NN) {
        int r = v;
        int s = g_offr[r], e = g_offr[r + 1];
        float base = g_normed[r] * g_nm[r];
        for (int i = s; i < e; i++) {
            int c = g_nbrr[i];
            ctr[i] = base * g_nm[c] / g_aggr[c];
        }
    }
}

// ----------------------------------------------------------------------------
// Per-level prep for levels 1,2 (3-phase grid-barrier kernel)
// ----------------------------------------------------------------------------
__global__ void __launch_bounds__(TB) k_prep(float* __restrict__ ecc,
                                             float* __restrict__ ctc,
                                             float* __restrict__ ctr) {
    int v = blockIdx.x * blockDim.x + threadIdx.x;
    if (v < NN) {
        int s = g_offr[v], e = g_offr[v + 1];
        float sum = 0.f;
        for (int i = s; i < e; i++) sum += g_nm[g_nbrr[i]];
        float d = g_nm[v] * sum;
        float dis_, nrm;
        if (d > 0.f) { dis_ = rsqrtf(d); nrm = g_w[v] / d; }
        else         { dis_ = 0.f; nrm = 0.f; }
        g_dis[v] = dis_;
        g_normed[v] = nrm;
    }
    gridbar();
    if (v < NN) {
        int c = v;
        int s = g_offc[c], e = g_offc[c + 1];
        float nmc = g_nm[c], disc = g_dis[c];
        float ag = 0.f;
        for (int i = s; i < e; i++) {
            int r = g_nbrc[i];
            ag = fmaf(g_normed[r], g_nm[r], ag);
        }
        float aggr = fmaf(nmc, ag, 1e-12f);
        g_aggr[c] = aggr;
        float inv = nmc / aggr;
        for (int i = s; i < e; i++) {
            int r = g_nbrc[i];
            ecc[i] = g_dis[r] * disc;
            if (ctc) ctc[i] = g_normed[r] * g_nm[r] * inv;
        }
    }
    if (!ctr) return;
    gridbar();
    if (v < NN) {
        int r = v;
        int s = g_offr[r], e = g_offr[r + 1];
        float base = g_normed[r] * g_nm[r];
        for (int i = s; i < e; i++) {
            int c = g_nbrr[i];
            ctr[i] = base * g_nm[c] / g_aggr[c];
        }
    }
}

// ----------------------------------------------------------------------------
// CSR pull-gather (warp per node, float4 per lane); optional node list.
// ----------------------------------------------------------------------------
template<bool SKIP, bool ADDIN, bool SCORE>
__global__ void __launch_bounds__(256) k_gather_t(
    const float* __restrict__ src, float* __restrict__ dst,
    const int* __restrict__ off, const int* __restrict__ nbr,
    const float* __restrict__ cf, const float* __restrict__ addin,
    const float* __restrict__ pv, int lvl,
    const int* __restrict__ list, int nlist) {
    int wid = (blockIdx.x * blockDim.x + threadIdx.x) >> 5;
    if (wid >= nlist) return;
    int v = list ? list[wid] : wid;
    int lane = threadIdx.x & 31;
    int s = off[v], e = off[v + 1];
    float ax = 0.f, ay = 0.f, az = 0.f, aw = 0.f;
    int i = s;
    if (!SKIP) {
        int e8 = s + ((e - s) & ~7);
        for (; i < e8; i += 8) {
            int n[8]; float w[8]; float4 t[8];
            #pragma unroll
            for (int u = 0; u < 8; u++) { n[u] = nbr[i + u]; w[u] = cf[i + u]; }
            #pragma unroll
            for (int u = 0; u < 8; u++)
                t[u] = ((const float4*)src)[(size_t)n[u] * 32 + lane];
            #pragma unroll
            for (int u = 0; u < 8; u++) {
                ax = fmaf(w[u], t[u].x, ax); ay = fmaf(w[u], t[u].y, ay);
                az = fmaf(w[u], t[u].z, az); aw = fmaf(w[u], t[u].w, aw);
            }
        }
    } else {
        for (; i + 4 <= e; i += 4) {
            int   n0 = nbr[i],   n1 = nbr[i+1],   n2 = nbr[i+2],   n3 = nbr[i+3];
            float w0 = cf[i],    w1 = cf[i+1],    w2 = cf[i+2],    w3 = cf[i+3];
            if (w0 != 0.f) {
                float4 t = ((const float4*)src)[(size_t)n0 * 32 + lane];
                ax = fmaf(w0, t.x, ax); ay = fmaf(w0, t.y, ay);
                az = fmaf(w0, t.z, az); aw = fmaf(w0, t.w, aw);
            }
            if (w1 != 0.f) {
                float4 t = ((const float4*)src)[(size_t)n1 * 32 + lane];
                ax = fmaf(w1, t.x, ax); ay = fmaf(w1, t.y, ay);
                az = fmaf(w1, t.z, az); aw = fmaf(w1, t.w, aw);
            }
            if (w2 != 0.f) {
                float4 t = ((const float4*)src)[(size_t)n2 * 32 + lane];
                ax = fmaf(w2, t.x, ax); ay = fmaf(w2, t.y, ay);
                az = fmaf(w2, t.z, az); aw = fmaf(w2, t.w, aw);
            }
            if (w3 != 0.f) {
                float4 t = ((const float4*)src)[(size_t)n3 * 32 + lane];
                ax = fmaf(w3, t.x, ax); ay = fmaf(w3, t.y, ay);
                az = fmaf(w3, t.z, az); aw = fmaf(w3, t.w, aw);
            }
        }
    }
    for (; i < e; i++) {
        int n = nbr[i]; float w = cf[i];
        if (!SKIP || w != 0.f) {
            float4 t = ((const float4*)src)[(size_t)n * 32 + lane];
            ax = fmaf(w, t.x, ax); ay = fmaf(w, t.y, ay);
            az = fmaf(w, t.z, az); aw = fmaf(w, t.w, aw);
        }
    }
    if (ADDIN) {
        float4 a = ((const float4*)addin)[(size_t)v * 32 + lane];
        ax += a.x; ay += a.y; az += a.z; aw += a.w;
    }
    ((float4*)dst)[(size_t)v * 32 + lane] = make_float4(ax, ay, az, aw);
    if (SCORE) {
        float4 p = ((const float4*)pv)[lane];
        float sdot = ax*p.x + ay*p.y + az*p.z + aw*p.w;
        #pragma unroll
        for (int o = 16; o; o >>= 1) sdot += __shfl_xor_sync(0xffffffffu, sdot, o);
        if (lane == 0) g_score[v] = sdot * g_pinv[lvl];
    }
}

// ----------------------------------------------------------------------------
// Dense GEMM: 128-row tile, 256 threads, 8x8/thread, k-step-4 with
// vectorized float4 sA loads, FFMA2.
// ----------------------------------------------------------------------------
#define GEMM_SMEM ((128*128 + 128*132) * 4)
__global__ void __launch_bounds__(256) k_gemm(const float* __restrict__ A,
                                              const float* __restrict__ W,
                                              const float* __restrict__ bias,
                                              float* __restrict__ C,
                                              const float* __restrict__ scale,
                                              const int* __restrict__ rowidx,
                                              int m) {
    extern __shared__ float sm[];
    float* sW = sm;              // [128][128]
    float* sA = sm + 128 * 128;  // [128][132] padded
    const int tid = threadIdx.x;
    const int row0 = blockIdx.x * 128;

    #pragma unroll 4
    for (int i = tid; i < 128 * 32; i += 256) {
        int r = i >> 5, c = (i & 31) << 2;
        *(float4*)(sW + r * 128 + c) = *(const float4*)(W + r * 128 + c);
    }
    #pragma unroll 4
    for (int i = tid; i < 128 * 32; i += 256) {
        int r = i >> 5, c = (i & 31) << 2;
        int rl = row0 + r;
        float4 v = make_float4(0.f, 0.f, 0.f, 0.f);
        if (rl < m) {
            int row = rowidx ? rowidx[rl] : rl;
            v = *(const float4*)(A + (size_t)row * DD + c);
            if (scale) {
                float sc = scale[row];
                v.x *= sc; v.y *= sc; v.z *= sc; v.w *= sc;
            }
        }
        *(float4*)(sA + r * 132 + c) = v;
    }
    __syncthreads();

    const int tx = tid & 15, ty = tid >> 4;
    const int rb = ty * 8, cb = tx * 8;
    unsigned long long acc[8][4] = {};

    #pragma unroll 2
    for (int k0 = 0; k0 < 128; k0 += 4) {
        float av[8][4];
        #pragma unroll
        for (int r = 0; r < 8; r++)
            *(float4*)av[r] = *(float4*)(sA + (rb + r) * 132 + k0);
        #pragma unroll
        for (int kk = 0; kk < 4; kk++) {
            ulonglong2 w0 = *(ulonglong2*)(sW + (k0 + kk) * 128 + cb);
            ulonglong2 w1 = *(ulonglong2*)(sW + (k0 + kk) * 128 + cb + 4);
            #pragma unroll
            for (int r = 0; r < 8; r++) {
                unsigned long long aa = pack2(av[r][kk]);
                acc[r][0] = fma2(aa, w0.x, acc[r][0]);
                acc[r][1] = fma2(aa, w0.y, acc[r][1]);
                acc[r][2] = fma2(aa, w1.x, acc[r][2]);
                acc[r][3] = fma2(aa, w1.y, acc[r][3]);
            }
        }
    }

    float4 b0 = *(const float4*)(bias + cb);
    float4 b1 = *(const float4*)(bias + cb + 4);
    #pragma unroll
    for (int r = 0; r < 8; r++) {
        int rl = row0 + rb + r;
        if (rl < m) {
            int row = rowidx ? rowidx[rl] : rl;
            float2 p0 = unpack2(acc[r][0]);
            float2 p1 = unpack2(acc[r][1]);
            float2 p2 = unpack2(acc[r][2]);
            float2 p3 = unpack2(acc[r][3]);
            float4 o0 = make_float4(p0.x + b0.x, p0.y + b0.y, p1.x + b0.z, p1.y + b0.w);
            float4 o1 = make_float4(p2.x + b1.x, p2.y + b1.y, p3.x + b1.z, p3.y + b1.w);
            *(float4*)(C + (size_t)row * DD + cb)     = o0;
            *(float4*)(C + (size_t)row * DD + cb + 4) = o1;
        }
    }
}

// ----------------------------------------------------------------------------
// TopK: keys fused with radix pass-0 count, 4x parallel scan, apply+compact
// ----------------------------------------------------------------------------
__global__ void k_keys(int kval) {
    int v = blockIdx.x * blockDim.x + threadIdx.x;
    if (v == 0) { g_prefix = 0ull; g_k = kval; }
    if (v >= NN) return;
    float s = (g_nm[v] > 0.f) ? g_score[v] : __int_as_float(0xff800000);
    unsigned u = __float_as_uint(s);
    u = (u & 0x80000000u) ? ~u : (u | 0x80000000u);
    unsigned long long key = ((unsigned long long)u << 32) |
                             (unsigned long long)(0xFFFFFFFFu - (unsigned)v);
    g_key[v] = key;
    atomicAdd(&g_hist[(unsigned)(key >> 48)], 1u);   // pass-0 count fused
}

__global__ void k_count(int pass) {
    int v = blockIdx.x * blockDim.x + threadIdx.x;
    if (v >= NN) return;
    unsigned long long key = g_key[v];
    if ((key >> (64 - 16 * pass)) != g_prefix) return;
    unsigned d = (unsigned)(key >> (48 - 16 * pass)) & 0xFFFFu;
    atomicAdd(&g_hist[d], 1u);
}

__global__ void k_scan() {
    __shared__ unsigned int sf[1024];
    int t = threadIdx.x;
    unsigned int s = 0;
    #pragma unroll 8
    for (int b = 0; b < 64; b++) s += g_hist[t * 64 + b];
    sf[t] = s;
    __syncthreads();
    for (int off = 1; off < 1024; off <<= 1) {
        unsigned int v = sf[t];
        unsigned int add = (t + off < 1024) ? sf[t + off] : 0u;
        __syncthreads();
        sf[t] = v + add;
        __syncthreads();
    }
    unsigned int k = (unsigned int)g_k;
    unsigned int above = (t < 1023) ? sf[t + 1] : 0u;
    if (above < k && sf[t] >= k) {
        unsigned int cum = above;
        int d = 0;
        for (int b = 63; b >= 0; b--) {
            unsigned int h = g_hist[t * 64 + b];
            if (cum + h >= k) { d = t * 64 + b; break; }
            cum += h;
        }
        g_prefix = (g_prefix << 16) | (unsigned long long)(unsigned)d;
        g_k = (int)(k - cum);
    }
    __syncthreads();
    #pragma unroll 8
    for (int b = 0; b < 64; b++) g_hist[t * 64 + b] = 0u;
}

__global__ void k_applynode(int* __restrict__ act, int* __restrict__ acnt) {
    int v = blockIdx.x * blockDim.x + threadIdx.x;
    if (v >= NN) return;
    bool kept = (g_key[v] >= g_prefix);
    g_nm[v] = kept ? 1.f : 0.f;
    g_w[v]  = kept ? g_aggr[v] : 0.f;
    g_s[v]  = kept ? tanhf(g_score[v]) : 0.f;
    if (kept) {
        int slot = atomicAdd(acnt, 1);
        act[slot] = v;
    }
}

// ----------------------------------------------------------------------------
// Host orchestration
// ----------------------------------------------------------------------------
extern "C" void kernel_launch(void* const* d_in, const int* in_sizes, int n_in,
                              void* d_out, int out_size) {
    const float* x_in = (const float*)d_in[0];
    const int*   ei   = (const int*)d_in[1];
    const float* Wd   = (const float*)d_in[2];
    const float* bd   = (const float*)d_in[3];
    const float* Wu   = (const float*)d_in[4];
    const float* bu   = (const float*)d_in[5];
    const float* Wb   = (const float*)d_in[6];
    const float* bb   = (const float*)d_in[7];
    const float* pvec = (const float*)d_in[8];
    float* out = (float*)d_out;

    float *p_h, *p_t, *p_g, *p_x, *p_d0, *p_d1;
    float *p_ecc0, *p_ecc1, *p_ecc2, *p_ctc0, *p_ctc1, *p_ctr0, *p_ctr1, *p_s;
    int *p_offr, *p_offc, *p_nbrr, *p_nbrc, *p_act0, *p_act1, *p_acnt0, *p_acnt1;
    cudaGetSymbolAddress((void**)&p_h, g_h);
    cudaGetSymbolAddress((void**)&p_t, g_t);
    cudaGetSymbolAddress((void**)&p_g, g_g);
    cudaGetSymbolAddress((void**)&p_x, g_xx);
    cudaGetSymbolAddress((void**)&p_d0, g_d0);
    cudaGetSymbolAddress((void**)&p_d1, g_d1);
    cudaGetSymbolAddress((void**)&p_ecc0, g_ecc0);
    cudaGetSymbolAddress((void**)&p_ecc1, g_ecc1);
    cudaGetSymbolAddress((void**)&p_ecc2, g_ecc2);
    cudaGetSymbolAddress((void**)&p_ctc0, g_ctc0);
    cudaGetSymbolAddress((void**)&p_ctc1, g_ctc1);
    cudaGetSymbolAddress((void**)&p_ctr0, g_ctr0);
    cudaGetSymbolAddress((void**)&p_ctr1, g_ctr1);
    cudaGetSymbolAddress((void**)&p_s, g_s);
    cudaGetSymbolAddress((void**)&p_offr, g_offr);
    cudaGetSymbolAddress((void**)&p_offc, g_offc);
    cudaGetSymbolAddress((void**)&p_nbrr, g_nbrr);
    cudaGetSymbolAddress((void**)&p_nbrc, g_nbrc);
    cudaGetSymbolAddress((void**)&p_act0, g_act0);
    cudaGetSymbolAddress((void**)&p_act1, g_act1);
    cudaGetSymbolAddress((void**)&p_acnt0, g_acnt0);
    cudaGetSymbolAddress((void**)&p_acnt1, g_acnt1);

    cudaFuncSetAttribute(k_gemm, cudaFuncAttributeMaxDynamicSharedMemorySize, GEMM_SMEM);

    const int G_N    = (NN + TB - 1) / TB;      // 196
    const int G_NW   = (NN * 32) / TB;          // 6250  (full gather)
    const int G_NW1  = (K1 * 32) / TB;          // 3125  (act0 gather)
    const int G_NW2  = (K2 * 32 + TB - 1) / TB; // 1563  (act1 gather)
    const int G_GF   = (NN + 127) / 128;        // 391
    const int G_G1   = (K1 + 127) / 128;        // 196
    const int G_G2   = (K2 + 127) / 128;        // 98

    // ---- prefix (R6 ordering) ----
    k_init_hist<<<PREP_GRID, TB>>>(pvec, ei);                                 // #1
    k_gemm<<<G_GF, TB, GEMM_SMEM>>>(x_in, Wd, bd, p_t, nullptr, nullptr, NN); // #2
    k_sfp<<<PREP_GRID, TB>>>(ei, p_ecc0, p_ctc0, p_ctr0);                     // #3
    k_gather_t<false,false,false><<<G_NW, TB>>>(p_t, p_g, p_offc, p_nbrc, p_ecc0,
                                                nullptr, nullptr, 0, nullptr, NN); // #4

    // ---- down level 0 (dense, continued) ----
    k_gemm<<<G_GF, TB, GEMM_SMEM>>>(p_g, Wd + (size_t)1*DD*DD, bd + 1*DD, p_t,
                                    nullptr, nullptr, NN);
    k_gather_t<false,false,false><<<G_NW, TB>>>(p_t, p_d0, p_offc, p_nbrc, p_ecc0,
                                                nullptr, nullptr, 0, nullptr, NN);
    k_gather_t<false,false,true><<<G_NW, TB>>>(p_d0, p_h, p_offc, p_nbrc, p_ctc0,
                                               nullptr, pvec, 0, nullptr, NN);
    k_keys<<<G_N, TB>>>(K1);
    k_scan<<<1, 1024>>>();
    for (int p = 1; p < 4; p++) { k_count<<<G_N, TB>>>(p); k_scan<<<1, 1024>>>(); }
    k_applynode<<<G_N, TB>>>(p_act0, p_acnt0);

    // ---- down level 1 (sparse; act0-compacted where legal) ----
    k_gemm<<<G_G1, TB, GEMM_SMEM>>>(p_h, Wd + (size_t)2*DD*DD, bd + 2*DD, p_t,
                                    p_s, p_act0, K1);
    k_prep<<<PREP_GRID, TB>>>(p_ecc1, p_ctc1, p_ctr1);
    k_gather_t<true,false,false><<<G_NW1, TB>>>(p_t, p_g, p_offc, p_nbrc, p_ecc1,
                                                nullptr, nullptr, 0, p_act0, K1);
    k_gemm<<<G_G1, TB, GEMM_SMEM>>>(p_g, Wd + (size_t)3*DD*DD, bd + 3*DD, p_t,
                                    nullptr, p_act0, K1);
    // d1 must be dense-valid (read as dense addin later) -> full gather
    k_gather_t<true,false,false><<<G_NW, TB>>>(p_t, p_d1, p_offc, p_nbrc, p_ecc1,
                                               nullptr, nullptr, 0, nullptr, NN);
    k_gather_t<true,false,true><<<G_NW1, TB>>>(p_d1, p_h, p_offc, p_nbrc, p_ctc1,
                                               nullptr, pvec + DD, 1, p_act0, K1);
    k_keys<<<G_N, TB>>>(K2);
    k_scan<<<1, 1024>>>();
    for (int p = 1; p < 4; p++) { k_count<<<G_N, TB>>>(p); k_scan<<<1, 1024>>>(); }
    k_applynode<<<G_N, TB>>>(p_act1, p_acnt1);

    // ---- bottom ----
    k_gemm<<<G_G2, TB, GEMM_SMEM>>>(p_h, Wb, bb, p_t, p_s, p_act1, K2);
    k_prep<<<PREP_GRID, TB>>>(p_ecc2, nullptr, nullptr);
    k_gather_t<true,false,false><<<G_NW2, TB>>>(p_t, p_g, p_offc, p_nbrc, p_ecc2,
                                                nullptr, nullptr, 0, p_act1, K2);
    k_gemm<<<G_G2, TB, GEMM_SMEM>>>(p_g, Wb + (size_t)1*DD*DD, bb + 1*DD, p_t,
                                    nullptr, p_act1, K2);
    // x must be valid for all act0 nodes (read by ctr1 gather) -> act0 list
    k_gather_t<true,false,false><<<G_NW1, TB>>>(p_t, p_x, p_offc, p_nbrc, p_ecc2,
                                                nullptr, nullptr, 0, p_act0, K1);

    // ---- up level 0 (act0 domain) ----
    k_gather_t<true,false,false><<<G_NW1, TB>>>(p_x, p_h, p_offr, p_nbrr, p_ctr1,
                                                nullptr, nullptr, 0, p_act0, K1);
    k_gemm<<<G_G1, TB, GEMM_SMEM>>>(p_h, Wu, bu, p_t, nullptr, p_act0, K1);
    k_gather_t<true,false,false><<<G_NW1, TB>>>(p_t, p_g, p_offc, p_nbrc, p_ecc1,
                                                nullptr, nullptr, 0, p_act0, K1);
    k_gemm<<<G_G1, TB, GEMM_SMEM>>>(p_g, Wu + (size_t)1*DD*DD, bu + 1*DD, p_t,
                                    nullptr, p_act0, K1);
    // x = gather + d1 must be dense-valid (read by dense ctr0 gather) -> full
    k_gather_t<true,true,false><<<G_NW, TB>>>(p_t, p_x, p_offc, p_nbrc, p_ecc1,
                                              p_d1, nullptr, 0, nullptr, NN);

    // ---- up level 1 (dense, full graph) ----
    k_gather_t<false,false,false><<<G_NW, TB>>>(p_x, p_h, p_offr, p_nbrr, p_ctr0,
                                                nullptr, nullptr, 0, nullptr, NN);
    k_gemm<<<G_GF, TB, GEMM_SMEM>>>(p_h, Wu + (size_t)2*DD*DD, bu + 2*DD, p_t,
                                    nullptr, nullptr, NN);
    k_gather_t<false,false,false><<<G_NW, TB>>>(p_t, p_g, p_offc, p_nbrc, p_ecc0,
                                                nullptr, nullptr, 0, nullptr, NN);
    k_gemm<<<G_GF, TB, GEMM_SMEM>>>(p_g, Wu + (size_t)3*DD*DD, bu + 3*DD, p_t,
                                    nullptr, nullptr, NN);
    k_gather_t<false,true,false><<<G_NW, TB>>>(p_t, out, p_offc, p_nbrc, p_ecc0,
                                               p_d0, nullptr, 0, nullptr, NN);
}

// round 10
// speedup vs baseline: 1.3691x; 1.2846x over previous
#include <cuda_runtime.h>
#include <cstdint>

// Problem constants
#define NN 50000
#define DD 128
#define EE 800000
#define ND (NN*DD)
#define TB 256
#define K1 25000
#define K2 12500
#define PREP_GRID 196            // ceil(NN/256)
#define GSTRIDE (PREP_GRID*TB)   // 50176
#define SCAN_GRID 64

// ----------------------------------------------------------------------------
// Device scratch (allocation-free: __device__ globals)
// ----------------------------------------------------------------------------
__device__ float g_h[ND];
__device__ float g_t[ND];
__device__ float g_g[ND];
__device__ float g_xx[ND];
__device__ float g_d0[ND];
__device__ float g_d1[ND];
__device__ int   g_nbrr[EE];
__device__ int   g_nbrc[EE];
__device__ float g_ecc0[EE];
__device__ float g_ecc1[EE];
__device__ float g_ecc2[EE];
__device__ float g_ctc0[EE];
__device__ float g_ctc1[EE];
__device__ float g_ctr0[EE];
__device__ float g_ctr1[EE];
__device__ float g_dis[NN];
__device__ float g_normed[NN];
__device__ float g_aggr[NN];
__device__ float g_w[NN];
__device__ float g_nm[NN];
__device__ float g_score[NN];
__device__ float g_s[NN];
__device__ unsigned long long g_key[NN];
__device__ unsigned int g_hist[65536];
__device__ unsigned int g_part2[SCAN_GRID];
__device__ unsigned long long g_prefix;
__device__ int g_k;
__device__ float g_pinv[2];
__device__ int g_cntr[NN];
__device__ int g_cntc[NN];
__device__ int g_offr[NN + 1];
__device__ int g_offc[NN + 1];
__device__ int g_curr[NN];
__device__ int g_curc[NN];
__device__ int g_act0[NN];
__device__ int g_act1[NN];
__device__ int g_acnt0;
__device__ int g_acnt1;
// software grid barrier — self-cleaning across graph replays; NEVER reset.
__device__ int g_barcnt = 0;
__device__ unsigned g_bargen = 0u;

// ----------------------------------------------------------------------------
// f32x2 packed-FMA helpers
// ----------------------------------------------------------------------------
__device__ __forceinline__ unsigned long long fma2(unsigned long long a,
                                                   unsigned long long b,
                                                   unsigned long long c) {
    unsigned long long d;
    asm("fma.rn.f32x2 %0, %1, %2, %3;" : "=l"(d) : "l"(a), "l"(b), "l"(c));
    return d;
}
__device__ __forceinline__ unsigned long long pack2(float x) {
    unsigned long long d;
    asm("mov.b64 %0, {%1, %1};" : "=l"(d) : "f"(x));
    return d;
}
__device__ __forceinline__ float2 unpack2(unsigned long long v) {
    float2 r;
    asm("mov.b64 {%0, %1}, %2;" : "=f"(r.x), "=f"(r.y) : "l"(v));
    return r;
}

// ----------------------------------------------------------------------------
// Software grid barrier (all blocks co-resident)
// ----------------------------------------------------------------------------
__device__ __forceinline__ void gridbar() {
    __syncthreads();
    if (threadIdx.x == 0) {
        unsigned gen = *((volatile unsigned*)&g_bargen);
        __threadfence();
        int ticket = atomicAdd(&g_barcnt, 1);
        if (ticket == (int)gridDim.x - 1) {
            g_barcnt = 0;
            __threadfence();
            atomicAdd(&g_bargen, 1u);
        } else {
            while (*((volatile unsigned*)&g_bargen) == gen) {}
        }
        __threadfence();
    }
    __syncthreads();
}

// ----------------------------------------------------------------------------
// Launch #1: init -> [bar] -> edge histogram
// ----------------------------------------------------------------------------
__global__ void __launch_bounds__(TB) k_init_hist(const float* __restrict__ pvec,
                                                  const int* __restrict__ ei) {
    int gid = blockIdx.x * blockDim.x + threadIdx.x;
    for (int j = gid; j < 65536; j += GSTRIDE) g_hist[j] = 0u;
    if (gid < NN) { g_nm[gid] = 1.0f; g_w[gid] = 1.0f; g_cntr[gid] = 0; g_cntc[gid] = 0; }
    if (gid == 0) { g_acnt0 = 0; g_acnt1 = 0; }
    if (blockIdx.x == 0 && threadIdx.x < 64) {
        int l = threadIdx.x >> 5, lane = threadIdx.x & 31;
        float4 p = ((const float4*)(pvec + l * DD))[lane];
        float s = p.x*p.x + p.y*p.y + p.z*p.z + p.w*p.w;
        #pragma unroll
        for (int o = 16; o; o >>= 1) s += __shfl_xor_sync(0xffffffffu, s, o);
        if (lane == 0) g_pinv[l] = rsqrtf(s);
    }
    gridbar();
    for (int e = gid; e < EE; e += GSTRIDE) {
        atomicAdd(&g_cntr[ei[e]], 1);
        atomicAdd(&g_cntc[ei[EE + e]], 1);
    }
}

// ----------------------------------------------------------------------------
// Launch #3: scans (block 0) -> [bar] -> csr fill -> [bar] -> level-0 prep
// ----------------------------------------------------------------------------
__device__ void scan256(const int* __restrict__ cnt, int* __restrict__ off,
                        int* __restrict__ cur, int* part) {
    const int PER = 196;   // 256*196 = 50176 >= NN
    int t = threadIdx.x;
    int base = t * PER;
    int s = 0;
    for (int i = 0; i < PER; i++) { int idx = base + i; if (idx < NN) s += cnt[idx]; }
    part[t] = s;
    __syncthreads();
    if (t == 0) {
        int acc = 0;
        for (int i = 0; i < 256; i++) { int v = part[i]; part[i] = acc; acc += v; }
        off[NN] = acc;
    }
    __syncthreads();
    int run = part[t];
    for (int i = 0; i < PER; i++) {
        int idx = base + i;
        if (idx < NN) { off[idx] = run; cur[idx] = run; run += cnt[idx]; }
    }
}

__global__ void __launch_bounds__(TB) k_sfp(const int* __restrict__ ei,
                                            float* __restrict__ ecc,
                                            float* __restrict__ ctc,
                                            float* __restrict__ ctr) {
    __shared__ int part[256];
    int gid = blockIdx.x * blockDim.x + threadIdx.x;
    if (blockIdx.x == 0) {
        scan256(g_cntr, g_offr, g_curr, part);
        __syncthreads();
        scan256(g_cntc, g_offc, g_curc, part);
    }
    gridbar();
    for (int e = gid; e < EE; e += GSTRIDE) {
        int r = ei[e], c = ei[EE + e];
        int pr = atomicAdd(&g_curr[r], 1);
        g_nbrr[pr] = c;
        int pc = atomicAdd(&g_curc[c], 1);
        g_nbrc[pc] = r;
    }
    gridbar();
    int v = gid;
    if (v < NN) {
        int s = g_offr[v], e = g_offr[v + 1];
        float sum = 0.f;
        for (int i = s; i < e; i++) sum += g_nm[g_nbrr[i]];
        float d = g_nm[v] * sum;
        float dis_, nrm;
        if (d > 0.f) { dis_ = rsqrtf(d); nrm = g_w[v] / d; }
        else         { dis_ = 0.f; nrm = 0.f; }
        g_dis[v] = dis_;
        g_normed[v] = nrm;
    }
    gridbar();
    if (v < NN) {
        int c = v;
        int s = g_offc[c], e = g_offc[c + 1];
        float nmc = g_nm[c], disc = g_dis[c];
        float ag = 0.f;
        for (int i = s; i < e; i++) {
            int r = g_nbrc[i];
            ag = fmaf(g_normed[r], g_nm[r], ag);
        }
        float aggr = fmaf(nmc, ag, 1e-12f);
        g_aggr[c] = aggr;
        float inv = nmc / aggr;
        for (int i = s; i < e; i++) {
            int r = g_nbrc[i];
            ecc[i] = g_dis[r] * disc;
            ctc[i] = g_normed[r] * g_nm[r] * inv;
        }
    }
    gridbar();
    if (v < NN) {
        int r = v;
        int s = g_offr[r], e = g_offr[r + 1];
        float base = g_normed[r] * g_nm[r];
        for (int i = s; i < e; i++) {
            int c = g_nbrr[i];
            ctr[i] = base * g_nm[c] / g_aggr[c];
        }
    }
}

// ----------------------------------------------------------------------------
// Per-level prep for levels 1,2
// ----------------------------------------------------------------------------
__global__ void __launch_bounds__(TB) k_prep(float* __restrict__ ecc,
                                             float* __restrict__ ctc,
                                             float* __restrict__ ctr) {
    int v = blockIdx.x * blockDim.x + threadIdx.x;
    if (v < NN) {
        int s = g_offr[v], e = g_offr[v + 1];
        float sum = 0.f;
        for (int i = s; i < e; i++) sum += g_nm[g_nbrr[i]];
        float d = g_nm[v] * sum;
        float dis_, nrm;
        if (d > 0.f) { dis_ = rsqrtf(d); nrm = g_w[v] / d; }
        else         { dis_ = 0.f; nrm = 0.f; }
        g_dis[v] = dis_;
        g_normed[v] = nrm;
    }
    gridbar();
    if (v < NN) {
        int c = v;
        int s = g_offc[c], e = g_offc[c + 1];
        float nmc = g_nm[c], disc = g_dis[c];
        float ag = 0.f;
        for (int i = s; i < e; i++) {
            int r = g_nbrc[i];
            ag = fmaf(g_normed[r], g_nm[r], ag);
        }
        float aggr = fmaf(nmc, ag, 1e-12f);
        g_aggr[c] = aggr;
        float inv = nmc / aggr;
        for (int i = s; i < e; i++) {
            int r = g_nbrc[i];
            ecc[i] = g_dis[r] * disc;
            if (ctc) ctc[i] = g_normed[r] * g_nm[r] * inv;
        }
    }
    if (!ctr) return;
    gridbar();
    if (v < NN) {
        int r = v;
        int s = g_offr[r], e = g_offr[r + 1];
        float base = g_normed[r] * g_nm[r];
        for (int i = s; i < e; i++) {
            int c = g_nbrr[i];
            ctr[i] = base * g_nm[c] / g_aggr[c];
        }
    }
}

// ----------------------------------------------------------------------------
// CSR pull-gather (warp per node, float4 per lane); optional node list.
// ----------------------------------------------------------------------------
template<bool SKIP, bool ADDIN, bool SCORE>
__global__ void __launch_bounds__(256) k_gather_t(
    const float* __restrict__ src, float* __restrict__ dst,
    const int* __restrict__ off, const int* __restrict__ nbr,
    const float* __restrict__ cf, const float* __restrict__ addin,
    const float* __restrict__ pv, int lvl,
    const int* __restrict__ list, int nlist) {
    int wid = (blockIdx.x * blockDim.x + threadIdx.x) >> 5;
    if (wid >= nlist) return;
    int v = list ? list[wid] : wid;
    int lane = threadIdx.x & 31;
    int s = off[v], e = off[v + 1];
    float ax = 0.f, ay = 0.f, az = 0.f, aw = 0.f;
    int i = s;
    if (!SKIP) {
        int e8 = s + ((e - s) & ~7);
        for (; i < e8; i += 8) {
            int n[8]; float w[8]; float4 t[8];
            #pragma unroll
            for (int u = 0; u < 8; u++) { n[u] = nbr[i + u]; w[u] = cf[i + u]; }
            #pragma unroll
            for (int u = 0; u < 8; u++)
                t[u] = ((const float4*)src)[(size_t)n[u] * 32 + lane];
            #pragma unroll
            for (int u = 0; u < 8; u++) {
                ax = fmaf(w[u], t[u].x, ax); ay = fmaf(w[u], t[u].y, ay);
                az = fmaf(w[u], t[u].z, az); aw = fmaf(w[u], t[u].w, aw);
            }
        }
    } else {
        for (; i + 4 <= e; i += 4) {
            int   n0 = nbr[i],   n1 = nbr[i+1],   n2 = nbr[i+2],   n3 = nbr[i+3];
            float w0 = cf[i],    w1 = cf[i+1],    w2 = cf[i+2],    w3 = cf[i+3];
            if (w0 != 0.f) {
                float4 t = ((const float4*)src)[(size_t)n0 * 32 + lane];
                ax = fmaf(w0, t.x, ax); ay = fmaf(w0, t.y, ay);
                az = fmaf(w0, t.z, az); aw = fmaf(w0, t.w, aw);
            }
            if (w1 != 0.f) {
                float4 t = ((const float4*)src)[(size_t)n1 * 32 + lane];
                ax = fmaf(w1, t.x, ax); ay = fmaf(w1, t.y, ay);
                az = fmaf(w1, t.z, az); aw = fmaf(w1, t.w, aw);
            }
            if (w2 != 0.f) {
                float4 t = ((const float4*)src)[(size_t)n2 * 32 + lane];
                ax = fmaf(w2, t.x, ax); ay = fmaf(w2, t.y, ay);
                az = fmaf(w2, t.z, az); aw = fmaf(w2, t.w, aw);
            }
            if (w3 != 0.f) {
                float4 t = ((const float4*)src)[(size_t)n3 * 32 + lane];
                ax = fmaf(w3, t.x, ax); ay = fmaf(w3, t.y, ay);
                az = fmaf(w3, t.z, az); aw = fmaf(w3, t.w, aw);
            }
        }
    }
    for (; i < e; i++) {
        int n = nbr[i]; float w = cf[i];
        if (!SKIP || w != 0.f) {
            float4 t = ((const float4*)src)[(size_t)n * 32 + lane];
            ax = fmaf(w, t.x, ax); ay = fmaf(w, t.y, ay);
            az = fmaf(w, t.z, az); aw = fmaf(w, t.w, aw);
        }
    }
    if (ADDIN) {
        float4 a = ((const float4*)addin)[(size_t)v * 32 + lane];
        ax += a.x; ay += a.y; az += a.z; aw += a.w;
    }
    ((float4*)dst)[(size_t)v * 32 + lane] = make_float4(ax, ay, az, aw);
    if (SCORE) {
        float4 p = ((const float4*)pv)[lane];
        float sdot = ax*p.x + ay*p.y + az*p.z + aw*p.w;
        #pragma unroll
        for (int o = 16; o; o >>= 1) sdot += __shfl_xor_sync(0xffffffffu, sdot, o);
        if (lane == 0) g_score[v] = sdot * g_pinv[lvl];
    }
}

// ----------------------------------------------------------------------------
// Dense GEMM v3: block = 128 rows x 64 cols, W-half in static smem (32KB),
// A streamed from L1 via broadcast LDG, 4x8/thread, FFMA2, scale in epilogue.
// grid = (ceil(m/128), 2)
// ----------------------------------------------------------------------------
__global__ void __launch_bounds__(256) k_gemm(const float* __restrict__ A,
                                              const float* __restrict__ W,
                                              const float* __restrict__ bias,
                                              float* __restrict__ C,
                                              const float* __restrict__ scale,
                                              const int* __restrict__ rowidx,
                                              int m) {
    __shared__ __align__(16) float sW[128 * 64];
    const int tid = threadIdx.x;
    const int row0 = blockIdx.x * 128;
    const int col0 = blockIdx.y * 64;

    // load W[k][col0 .. col0+64)
    #pragma unroll 4
    for (int i = tid; i < 128 * 16; i += 256) {
        int r = i >> 4, c = (i & 15) << 2;
        *(float4*)(sW + r * 64 + c) = *(const float4*)(W + r * DD + col0 + c);
    }
    __syncthreads();

    const int tx = tid & 7, ty = tid >> 3;   // 8 col groups x 32 row groups
    const int cb = tx * 8;
    const int rb = ty * 4;

    int rowv[4]; float scv[4]; bool vl[4];
    #pragma unroll
    for (int r = 0; r < 4; r++) {
        int rl = row0 + rb + r;
        vl[r] = (rl < m);
        int row = vl[r] ? (rowidx ? rowidx[rl] : rl) : 0;
        rowv[r] = row;
        scv[r] = (scale && vl[r]) ? scale[row] : 1.f;
    }

    unsigned long long acc[4][4] = {};

    #pragma unroll 2
    for (int k0 = 0; k0 < 128; k0 += 4) {
        float av[4][4];
        #pragma unroll
        for (int r = 0; r < 4; r++) {
            float4 v = vl[r] ? *(const float4*)(A + (size_t)rowv[r] * DD + k0)
                             : make_float4(0.f, 0.f, 0.f, 0.f);
            av[r][0] = v.x; av[r][1] = v.y; av[r][2] = v.z; av[r][3] = v.w;
        }
        #pragma unroll
        for (int kk = 0; kk < 4; kk++) {
            ulonglong2 w0 = *(ulonglong2*)(sW + (k0 + kk) * 64 + cb);
            ulonglong2 w1 = *(ulonglong2*)(sW + (k0 + kk) * 64 + cb + 4);
            #pragma unroll
            for (int r = 0; r < 4; r++) {
                unsigned long long aa = pack2(av[r][kk]);
                acc[r][0] = fma2(aa, w0.x, acc[r][0]);
                acc[r][1] = fma2(aa, w0.y, acc[r][1]);
                acc[r][2] = fma2(aa, w1.x, acc[r][2]);
                acc[r][3] = fma2(aa, w1.y, acc[r][3]);
            }
        }
    }

    float4 b0 = *(const float4*)(bias + col0 + cb);
    float4 b1 = *(const float4*)(bias + col0 + cb + 4);
    #pragma unroll
    for (int r = 0; r < 4; r++) {
        if (vl[r]) {
            float s = scv[r];
            float2 p0 = unpack2(acc[r][0]);
            float2 p1 = unpack2(acc[r][1]);
            float2 p2 = unpack2(acc[r][2]);
            float2 p3 = unpack2(acc[r][3]);
            float4 o0 = make_float4(fmaf(s, p0.x, b0.x), fmaf(s, p0.y, b0.y),
                                    fmaf(s, p1.x, b0.z), fmaf(s, p1.y, b0.w));
            float4 o1 = make_float4(fmaf(s, p2.x, b1.x), fmaf(s, p2.y, b1.y),
                                    fmaf(s, p3.x, b1.z), fmaf(s, p3.y, b1.w));
            float* cp = C + (size_t)rowv[r] * DD + col0 + cb;
            *(float4*)(cp)     = o0;
            *(float4*)(cp + 4) = o1;
        }
    }
}

// ----------------------------------------------------------------------------
// TopK: 48-bit keys (score<<16 | (65535-v)), 3 radix passes of 16 bits.
// keys fused with pass-0 count; parallel 64-block scan; apply+compact.
// ----------------------------------------------------------------------------
__global__ void k_keys(int kval) {
    int v = blockIdx.x * blockDim.x + threadIdx.x;
    if (v == 0) { g_prefix = 0ull; g_k = kval; }
    if (v >= NN) return;
    float s = (g_nm[v] > 0.f) ? g_score[v] : __int_as_float(0xff800000);
    unsigned u = __float_as_uint(s);
    u = (u & 0x80000000u) ? ~u : (u | 0x80000000u);
    unsigned long long key = ((unsigned long long)u << 16) |
                             (unsigned long long)(65535u - (unsigned)v);
    g_key[v] = key;
    atomicAdd(&g_hist[(unsigned)(key >> 32)], 1u);   // pass-0 count fused
}

__global__ void k_count(int pass) {   // pass in {1,2}
    int v = blockIdx.x * blockDim.x + threadIdx.x;
    if (v >= NN) return;
    unsigned long long key = g_key[v];
    if ((key >> (48 - 16 * pass)) != g_prefix) return;
    unsigned d = (unsigned)(key >> (32 - 16 * pass)) & 0xFFFFu;
    atomicAdd(&g_hist[d], 1u);
}

// parallel radix-select scan: SCAN_GRID blocks x 256 threads
__global__ void __launch_bounds__(256) k_scanp() {
    __shared__ unsigned red[256];
    __shared__ unsigned sf[256];
    __shared__ int sel_b;
    __shared__ unsigned sel_cum;
    int b = blockIdx.x, t = threadIdx.x;
    int base = b * 1024;

    // phase 1: per-block slice sum (1024 entries each)
    unsigned s = 0;
    #pragma unroll
    for (int i = 0; i < 4; i++) s += g_hist[base + t + i * 256];
    red[t] = s;
    __syncthreads();
    for (int o = 128; o; o >>= 1) { if (t < o) red[t] += red[t + o]; __syncthreads(); }
    if (t == 0) g_part2[b] = red[0];
    gridbar();

    // phase 2: block 0 locates threshold slice + digit
    if (b == 0) {
        if (t == 0) {
            unsigned k = (unsigned)g_k;
            unsigned cum = 0;
            int bb = 0;
            for (bb = SCAN_GRID - 1; bb > 0; bb--) {
                unsigned p = g_part2[bb];
                if (cum + p >= k) break;
                cum += p;
            }
            sel_b = bb;
            sel_cum = cum;
        }
        __syncthreads();
        int bb = sel_b;
        unsigned kk = (unsigned)g_k - sel_cum;
        int sbase = bb * 1024 + t * 4;
        unsigned h0 = g_hist[sbase], h1 = g_hist[sbase + 1];
        unsigned h2 = g_hist[sbase + 2], h3 = g_hist[sbase + 3];
        unsigned gs = h0 + h1 + h2 + h3;
        sf[t] = gs;
        __syncthreads();
        for (int off = 1; off < 256; off <<= 1) {
            unsigned v = sf[t];
            unsigned ad = (t + off < 256) ? sf[t + off] : 0u;
            __syncthreads();
            sf[t] = v + ad;
            __syncthreads();
        }
        unsigned above = (t < 255) ? sf[t + 1] : 0u;
        if (above < kk && sf[t] >= kk) {
            unsigned cum = above;
            int d = sbase;
            if (cum + h3 >= kk)              { d = sbase + 3; }
            else if (cum + h3 + h2 >= kk)    { cum += h3; d = sbase + 2; }
            else if (cum + h3 + h2 + h1 >= kk){ cum += h3 + h2; d = sbase + 1; }
            else                             { cum += h3 + h2 + h1; d = sbase; }
            g_prefix = (g_prefix << 16) | (unsigned long long)(unsigned)d;
            g_k = (int)(kk - cum);
        }
    }
    gridbar();

    // phase 3: zero slices
    #pragma unroll
    for (int i = 0; i < 4; i++) g_hist[base + t + i * 256] = 0u;
}

__global__ void k_applynode(int* __restrict__ act, int* __restrict__ acnt) {
    int v = blockIdx.x * blockDim.x + threadIdx.x;
    if (v >= NN) return;
    bool kept = (g_key[v] >= g_prefix);
    g_nm[v] = kept ? 1.f : 0.f;
    g_w[v]  = kept ? g_aggr[v] : 0.f;
    g_s[v]  = kept ? tanhf(g_score[v]) : 0.f;
    if (kept) {
        int slot = atomicAdd(acnt, 1);
        act[slot] = v;
    }
}

// ----------------------------------------------------------------------------
// Host orchestration
// ----------------------------------------------------------------------------
extern "C" void kernel_launch(void* const* d_in, const int* in_sizes, int n_in,
                              void* d_out, int out_size) {
    const float* x_in = (const float*)d_in[0];
    const int*   ei   = (const int*)d_in[1];
    const float* Wd   = (const float*)d_in[2];
    const float* bd   = (const float*)d_in[3];
    const float* Wu   = (const float*)d_in[4];
    const float* bu   = (const float*)d_in[5];
    const float* Wb   = (const float*)d_in[6];
    const float* bb   = (const float*)d_in[7];
    const float* pvec = (const float*)d_in[8];
    float* out = (float*)d_out;

    float *p_h, *p_t, *p_g, *p_x, *p_d0, *p_d1;
    float *p_ecc0, *p_ecc1, *p_ecc2, *p_ctc0, *p_ctc1, *p_ctr0, *p_ctr1, *p_s;
    int *p_offr, *p_offc, *p_nbrr, *p_nbrc, *p_act0, *p_act1, *p_acnt0, *p_acnt1;
    cudaGetSymbolAddress((void**)&p_h, g_h);
    cudaGetSymbolAddress((void**)&p_t, g_t);
    cudaGetSymbolAddress((void**)&p_g, g_g);
    cudaGetSymbolAddress((void**)&p_x, g_xx);
    cudaGetSymbolAddress((void**)&p_d0, g_d0);
    cudaGetSymbolAddress((void**)&p_d1, g_d1);
    cudaGetSymbolAddress((void**)&p_ecc0, g_ecc0);
    cudaGetSymbolAddress((void**)&p_ecc1, g_ecc1);
    cudaGetSymbolAddress((void**)&p_ecc2, g_ecc2);
    cudaGetSymbolAddress((void**)&p_ctc0, g_ctc0);
    cudaGetSymbolAddress((void**)&p_ctc1, g_ctc1);
    cudaGetSymbolAddress((void**)&p_ctr0, g_ctr0);
    cudaGetSymbolAddress((void**)&p_ctr1, g_ctr1);
    cudaGetSymbolAddress((void**)&p_s, g_s);
    cudaGetSymbolAddress((void**)&p_offr, g_offr);
    cudaGetSymbolAddress((void**)&p_offc, g_offc);
    cudaGetSymbolAddress((void**)&p_nbrr, g_nbrr);
    cudaGetSymbolAddress((void**)&p_nbrc, g_nbrc);
    cudaGetSymbolAddress((void**)&p_act0, g_act0);
    cudaGetSymbolAddress((void**)&p_act1, g_act1);
    cudaGetSymbolAddress((void**)&p_acnt0, g_acnt0);
    cudaGetSymbolAddress((void**)&p_acnt1, g_acnt1);

    const int G_N    = (NN + TB - 1) / TB;      // 196
    const int G_NW   = (NN * 32) / TB;          // 6250  (full gather)
    const int G_NW1  = (K1 * 32) / TB;          // 3125  (act0 gather)
    const int G_NW2  = (K2 * 32 + TB - 1) / TB; // 1563  (act1 gather)
    const dim3 G_GF((NN + 127) / 128, 2);       // 391 x 2
    const dim3 G_G1((K1 + 127) / 128, 2);       // 196 x 2
    const dim3 G_G2((K2 + 127) / 128, 2);       // 98 x 2

    // ---- prefix ----
    k_init_hist<<<PREP_GRID, TB>>>(pvec, ei);                                 // #1
    k_gemm<<<G_GF, TB>>>(x_in, Wd, bd, p_t, nullptr, nullptr, NN);            // #2
    k_sfp<<<PREP_GRID, TB>>>(ei, p_ecc0, p_ctc0, p_ctr0);                     // #3
    k_gather_t<false,false,false><<<G_NW, TB>>>(p_t, p_g, p_offc, p_nbrc, p_ecc0,
                                                nullptr, nullptr, 0, nullptr, NN); // #4

    // ---- down level 0 (dense) ----
    k_gemm<<<G_GF, TB>>>(p_g, Wd + (size_t)1*DD*DD, bd + 1*DD, p_t,
                         nullptr, nullptr, NN);
    k_gather_t<false,false,false><<<G_NW, TB>>>(p_t, p_d0, p_offc, p_nbrc, p_ecc0,
                                                nullptr, nullptr, 0, nullptr, NN);
    k_gather_t<false,false,true><<<G_NW, TB>>>(p_d0, p_h, p_offc, p_nbrc, p_ctc0,
                                               nullptr, pvec, 0, nullptr, NN);
    k_keys<<<G_N, TB>>>(K1);
    k_scanp<<<SCAN_GRID, 256>>>();
    for (int p = 1; p < 3; p++) { k_count<<<G_N, TB>>>(p); k_scanp<<<SCAN_GRID, 256>>>(); }
    k_applynode<<<G_N, TB>>>(p_act0, p_acnt0);

    // ---- down level 1 (sparse; act0-compacted where legal) ----
    k_gemm<<<G_G1, TB>>>(p_h, Wd + (size_t)2*DD*DD, bd + 2*DD, p_t,
                         p_s, p_act0, K1);
    k_prep<<<PREP_GRID, TB>>>(p_ecc1, p_ctc1, p_ctr1);
    k_gather_t<true,false,false><<<G_NW1, TB>>>(p_t, p_g, p_offc, p_nbrc, p_ecc1,
                                                nullptr, nullptr, 0, p_act0, K1);
    k_gemm<<<G_G1, TB>>>(p_g, Wd + (size_t)3*DD*DD, bd + 3*DD, p_t,
                         nullptr, p_act0, K1);
    // d1 must be dense-valid (read as dense addin later) -> full gather
    k_gather_t<true,false,false><<<G_NW, TB>>>(p_t, p_d1, p_offc, p_nbrc, p_ecc1,
                                               nullptr, nullptr, 0, nullptr, NN);
    k_gather_t<true,false,true><<<G_NW1, TB>>>(p_d1, p_h, p_offc, p_nbrc, p_ctc1,
                                               nullptr, pvec + DD, 1, p_act0, K1);
    k_keys<<<G_N, TB>>>(K2);
    k_scanp<<<SCAN_GRID, 256>>>();
    for (int p = 1; p < 3; p++) { k_count<<<G_N, TB>>>(p); k_scanp<<<SCAN_GRID, 256>>>(); }
    k_applynode<<<G_N, TB>>>(p_act1, p_acnt1);

    // ---- bottom ----
    k_gemm<<<G_G2, TB>>>(p_h, Wb, bb, p_t, p_s, p_act1, K2);
    k_prep<<<PREP_GRID, TB>>>(p_ecc2, nullptr, nullptr);
    k_gather_t<true,false,false><<<G_NW2, TB>>>(p_t, p_g, p_offc, p_nbrc, p_ecc2,
                                                nullptr, nullptr, 0, p_act1, K2);
    k_gemm<<<G_G2, TB>>>(p_g, Wb + (size_t)1*DD*DD, bb + 1*DD, p_t,
                         nullptr, p_act1, K2);
    // x must be valid for all act0 nodes (read by ctr1 gather) -> act0 list
    k_gather_t<true,false,false><<<G_NW1, TB>>>(p_t, p_x, p_offc, p_nbrc, p_ecc2,
                                                nullptr, nullptr, 0, p_act0, K1);

    // ---- up level 0 (act0 domain) ----
    k_gather_t<true,false,false><<<G_NW1, TB>>>(p_x, p_h, p_offr, p_nbrr, p_ctr1,
                                                nullptr, nullptr, 0, p_act0, K1);
    k_gemm<<<G_G1, TB>>>(p_h, Wu, bu, p_t, nullptr, p_act0, K1);
    k_gather_t<true,false,false><<<G_NW1, TB>>>(p_t, p_g, p_offc, p_nbrc, p_ecc1,
                                                nullptr, nullptr, 0, p_act0, K1);
    k_gemm<<<G_G1, TB>>>(p_g, Wu + (size_t)1*DD*DD, bu + 1*DD, p_t,
                         nullptr, p_act0, K1);
    // x = gather + d1 must be dense-valid (read by dense ctr0 gather) -> full
    k_gather_t<true,true,false><<<G_NW, TB>>>(p_t, p_x, p_offc, p_nbrc, p_ecc1,
                                              p_d1, nullptr, 0, nullptr, NN);

    // ---- up level 1 (dense, full graph) ----
    k_gather_t<false,false,false><<<G_NW, TB>>>(p_x, p_h, p_offr, p_nbrr, p_ctr0,
                                                nullptr, nullptr, 0, nullptr, NN);
    k_gemm<<<G_GF, TB>>>(p_h, Wu + (size_t)2*DD*DD, bu + 2*DD, p_t,
                         nullptr, nullptr, NN);
    k_gather_t<false,false,false><<<G_NW, TB>>>(p_t, p_g, p_offc, p_nbrc, p_ecc0,
                                                nullptr, nullptr, 0, nullptr, NN);
    k_gemm<<<G_GF, TB>>>(p_g, Wu + (size_t)3*DD*DD, bu + 3*DD, p_t,
                         nullptr, nullptr, NN);
    k_gather_t<false,true,false><<<G_NW, TB>>>(p_t, out, p_offc, p_nbrc, p_ecc0,
                                               p_d0, nullptr, 0, nullptr, NN);
}

// round 11
// speedup vs baseline: 1.3978x; 1.0210x over previous
#include <cuda_runtime.h>
#include <cstdint>

// Problem constants
#define NN 50000
#define DD 128
#define EE 800000
#define ND (NN*DD)
#define TB 256
#define K1 25000
#define K2 12500
#define PREP_GRID 196            // ceil(NN/256)
#define GSTRIDE (PREP_GRID*TB)   // 50176
#define SCAN_GRID 64

// ----------------------------------------------------------------------------
// Device scratch (allocation-free: __device__ globals)
// ----------------------------------------------------------------------------
__device__ float g_h[ND];
__device__ float g_t[ND];
__device__ float g_g[ND];
__device__ float g_xx[ND];
__device__ float g_d0[ND];
__device__ float g_d1[ND];
__device__ int   g_nbrr[EE];
__device__ int   g_nbrc[EE];
__device__ float g_ecc0[EE];
__device__ float g_ecc1[EE];
__device__ float g_ecc2[EE];
__device__ float g_ctc0[EE];
__device__ float g_ctc1[EE];
__device__ float g_ctr0[EE];
__device__ float g_ctr1[EE];
// packed node state: x=nm, y=normed, z=dis, w=aggr
__device__ float4 g_node[NN];
__device__ float g_w[NN];
__device__ float g_score[NN];
__device__ float g_s[NN];
__device__ unsigned long long g_key[NN];
__device__ unsigned int g_hist[65536];
__device__ unsigned int g_part2[SCAN_GRID];
__device__ unsigned long long g_prefix;
__device__ int g_k;
__device__ float g_pinv[2];
__device__ int g_cntr[NN];
__device__ int g_cntc[NN];
__device__ int g_offr[NN + 1];
__device__ int g_offc[NN + 1];
__device__ int g_curr[NN];
__device__ int g_curc[NN];
__device__ int g_act0[NN];
__device__ int g_act1[NN];
__device__ int g_acnt0;
__device__ int g_acnt1;
// software grid barrier — self-cleaning across graph replays; NEVER reset.
__device__ int g_barcnt = 0;
__device__ unsigned g_bargen = 0u;

// ----------------------------------------------------------------------------
// f32x2 packed-FMA helpers
// ----------------------------------------------------------------------------
__device__ __forceinline__ unsigned long long fma2(unsigned long long a,
                                                   unsigned long long b,
                                                   unsigned long long c) {
    unsigned long long d;
    asm("fma.rn.f32x2 %0, %1, %2, %3;" : "=l"(d) : "l"(a), "l"(b), "l"(c));
    return d;
}
__device__ __forceinline__ unsigned long long pack2(float x) {
    unsigned long long d;
    asm("mov.b64 %0, {%1, %1};" : "=l"(d) : "f"(x));
    return d;
}
__device__ __forceinline__ float2 unpack2(unsigned long long v) {
    float2 r;
    asm("mov.b64 {%0, %1}, %2;" : "=f"(r.x), "=f"(r.y) : "l"(v));
    return r;
}

// ----------------------------------------------------------------------------
// Software grid barrier (all blocks co-resident)
// ----------------------------------------------------------------------------
__device__ __forceinline__ void gridbar() {
    __syncthreads();
    if (threadIdx.x == 0) {
        unsigned gen = *((volatile unsigned*)&g_bargen);
        __threadfence();
        int ticket = atomicAdd(&g_barcnt, 1);
        if (ticket == (int)gridDim.x - 1) {
            g_barcnt = 0;
            __threadfence();
            atomicAdd(&g_bargen, 1u);
        } else {
            while (*((volatile unsigned*)&g_bargen) == gen) {}
        }
        __threadfence();
    }
    __syncthreads();
}

// ----------------------------------------------------------------------------
// Launch #1: init -> [bar] -> edge histogram
// ----------------------------------------------------------------------------
__global__ void __launch_bounds__(TB) k_init_hist(const float* __restrict__ pvec,
                                                  const int* __restrict__ ei) {
    int gid = blockIdx.x * blockDim.x + threadIdx.x;
    for (int j = gid; j < 65536; j += GSTRIDE) g_hist[j] = 0u;
    if (gid < NN) {
        g_node[gid] = make_float4(1.f, 0.f, 0.f, 0.f);
        g_w[gid] = 1.0f;
        g_cntr[gid] = 0; g_cntc[gid] = 0;
    }
    if (gid == 0) { g_acnt0 = 0; g_acnt1 = 0; }
    if (blockIdx.x == 0 && threadIdx.x < 64) {
        int l = threadIdx.x >> 5, lane = threadIdx.x & 31;
        float4 p = ((const float4*)(pvec + l * DD))[lane];
        float s = p.x*p.x + p.y*p.y + p.z*p.z + p.w*p.w;
        #pragma unroll
        for (int o = 16; o; o >>= 1) s += __shfl_xor_sync(0xffffffffu, s, o);
        if (lane == 0) g_pinv[l] = rsqrtf(s);
    }
    gridbar();
    for (int e = gid; e < EE; e += GSTRIDE) {
        atomicAdd(&g_cntr[ei[e]], 1);
        atomicAdd(&g_cntc[ei[EE + e]], 1);
    }
}

// ----------------------------------------------------------------------------
// Launch #3: scans (block 0) -> [bar] -> csr fill
// ----------------------------------------------------------------------------
__device__ void scan256(const int* __restrict__ cnt, int* __restrict__ off,
                        int* __restrict__ cur, int* part) {
    const int PER = 196;   // 256*196 = 50176 >= NN
    int t = threadIdx.x;
    int base = t * PER;
    int s = 0;
    for (int i = 0; i < PER; i++) { int idx = base + i; if (idx < NN) s += cnt[idx]; }
    part[t] = s;
    __syncthreads();
    if (t == 0) {
        int acc = 0;
        for (int i = 0; i < 256; i++) { int v = part[i]; part[i] = acc; acc += v; }
        off[NN] = acc;
    }
    __syncthreads();
    int run = part[t];
    for (int i = 0; i < PER; i++) {
        int idx = base + i;
        if (idx < NN) { off[idx] = run; cur[idx] = run; run += cnt[idx]; }
    }
}

__global__ void __launch_bounds__(TB) k_scanfill(const int* __restrict__ ei) {
    __shared__ int part[256];
    int gid = blockIdx.x * blockDim.x + threadIdx.x;
    if (blockIdx.x == 0) {
        scan256(g_cntr, g_offr, g_curr, part);
        __syncthreads();
        scan256(g_cntc, g_offc, g_curc, part);
    }
    gridbar();
    for (int e = gid; e < EE; e += GSTRIDE) {
        int r = ei[e], c = ei[EE + e];
        int pr = atomicAdd(&g_curr[r], 1);
        g_nbrr[pr] = c;
        int pc = atomicAdd(&g_curc[c], 1);
        g_nbrc[pc] = r;
    }
}

// ----------------------------------------------------------------------------
// Per-level prep (3-phase grid-barrier, packed node state)
// ----------------------------------------------------------------------------
__global__ void __launch_bounds__(TB) k_prep(float* __restrict__ ecc,
                                             float* __restrict__ ctc,
                                             float* __restrict__ ctr) {
    int v = blockIdx.x * blockDim.x + threadIdx.x;
    // phase 1: deg -> dis, normed
    if (v < NN) {
        int s = g_offr[v], e = g_offr[v + 1];
        float sum = 0.f;
        for (int i = s; i < e; i++) sum += g_node[g_nbrr[i]].x;
        float4 n4 = g_node[v];
        float d = n4.x * sum;
        if (d > 0.f) { n4.z = rsqrtf(d); n4.y = g_w[v] / d; }
        else         { n4.z = 0.f; n4.y = 0.f; }
        g_node[v] = n4;
    }
    gridbar();
    // phase 2: aggr + ecc/ctc (1 packed random sector per edge)
    if (v < NN) {
        int c = v;
        int s = g_offc[c], e = g_offc[c + 1];
        float4 n4c = g_node[c];
        float nmc = n4c.x, disc = n4c.z;
        float ag = 0.f;
        for (int i = s; i < e; i++) {
            float4 nr = g_node[g_nbrc[i]];
            ag = fmaf(nr.y, nr.x, ag);
        }
        float aggr = fmaf(nmc, ag, 1e-12f);
        n4c.w = aggr;
        g_node[c] = n4c;
        float inv = nmc / aggr;
        for (int i = s; i < e; i++) {
            float4 nr = g_node[g_nbrc[i]];
            ecc[i] = nr.z * disc;
            if (ctc) ctc[i] = nr.y * nr.x * inv;
        }
    }
    if (!ctr) return;
    gridbar();
    // phase 3: ctr
    if (v < NN) {
        int r = v;
        int s = g_offr[r], e = g_offr[r + 1];
        float4 n4r = g_node[r];
        float base = n4r.y * n4r.x;
        for (int i = s; i < e; i++) {
            float4 nc = g_node[g_nbrr[i]];
            ctr[i] = base * nc.x / nc.w;
        }
    }
}

// ----------------------------------------------------------------------------
// CSR pull-gather (warp per node, float4 per lane); optional node list.
// ----------------------------------------------------------------------------
template<bool SKIP, bool ADDIN, bool SCORE>
__global__ void __launch_bounds__(256) k_gather_t(
    const float* __restrict__ src, float* __restrict__ dst,
    const int* __restrict__ off, const int* __restrict__ nbr,
    const float* __restrict__ cf, const float* __restrict__ addin,
    const float* __restrict__ pv, int lvl,
    const int* __restrict__ list, int nlist) {
    int wid = (blockIdx.x * blockDim.x + threadIdx.x) >> 5;
    if (wid >= nlist) return;
    int v = list ? list[wid] : wid;
    int lane = threadIdx.x & 31;
    int s = off[v], e = off[v + 1];
    float ax = 0.f, ay = 0.f, az = 0.f, aw = 0.f;
    int i = s;
    if (!SKIP) {
        int e8 = s + ((e - s) & ~7);
        for (; i < e8; i += 8) {
            int n[8]; float w[8]; float4 t[8];
            #pragma unroll
            for (int u = 0; u < 8; u++) { n[u] = nbr[i + u]; w[u] = cf[i + u]; }
            #pragma unroll
            for (int u = 0; u < 8; u++)
                t[u] = ((const float4*)src)[(size_t)n[u] * 32 + lane];
            #pragma unroll
            for (int u = 0; u < 8; u++) {
                ax = fmaf(w[u], t[u].x, ax); ay = fmaf(w[u], t[u].y, ay);
                az = fmaf(w[u], t[u].z, az); aw = fmaf(w[u], t[u].w, aw);
            }
        }
    } else {
        for (; i + 4 <= e; i += 4) {
            int   n0 = nbr[i],   n1 = nbr[i+1],   n2 = nbr[i+2],   n3 = nbr[i+3];
            float w0 = cf[i],    w1 = cf[i+1],    w2 = cf[i+2],    w3 = cf[i+3];
            if (w0 != 0.f) {
                float4 t = ((const float4*)src)[(size_t)n0 * 32 + lane];
                ax = fmaf(w0, t.x, ax); ay = fmaf(w0, t.y, ay);
                az = fmaf(w0, t.z, az); aw = fmaf(w0, t.w, aw);
            }
            if (w1 != 0.f) {
                float4 t = ((const float4*)src)[(size_t)n1 * 32 + lane];
                ax = fmaf(w1, t.x, ax); ay = fmaf(w1, t.y, ay);
                az = fmaf(w1, t.z, az); aw = fmaf(w1, t.w, aw);
            }
            if (w2 != 0.f) {
                float4 t = ((const float4*)src)[(size_t)n2 * 32 + lane];
                ax = fmaf(w2, t.x, ax); ay = fmaf(w2, t.y, ay);
                az = fmaf(w2, t.z, az); aw = fmaf(w2, t.w, aw);
            }
            if (w3 != 0.f) {
                float4 t = ((const float4*)src)[(size_t)n3 * 32 + lane];
                ax = fmaf(w3, t.x, ax); ay = fmaf(w3, t.y, ay);
                az = fmaf(w3, t.z, az); aw = fmaf(w3, t.w, aw);
            }
        }
    }
    for (; i < e; i++) {
        int n = nbr[i]; float w = cf[i];
        if (!SKIP || w != 0.f) {
            float4 t = ((const float4*)src)[(size_t)n * 32 + lane];
            ax = fmaf(w, t.x, ax); ay = fmaf(w, t.y, ay);
            az = fmaf(w, t.z, az); aw = fmaf(w, t.w, aw);
        }
    }
    if (ADDIN) {
        float4 a = ((const float4*)addin)[(size_t)v * 32 + lane];
        ax += a.x; ay += a.y; az += a.z; aw += a.w;
    }
    ((float4*)dst)[(size_t)v * 32 + lane] = make_float4(ax, ay, az, aw);
    if (SCORE) {
        float4 p = ((const float4*)pv)[lane];
        float sdot = ax*p.x + ay*p.y + az*p.z + aw*p.w;
        #pragma unroll
        for (int o = 16; o; o >>= 1) sdot += __shfl_xor_sync(0xffffffffu, sdot, o);
        if (lane == 0) g_score[v] = sdot * g_pinv[lvl];
    }
}

// ----------------------------------------------------------------------------
// Dense GEMM v3: block = 128 rows x 64 cols, W-half in static smem (32KB),
// A streamed from L1 via broadcast LDG, 4x8/thread, FFMA2, scale in epilogue.
// grid = (ceil(m/128), 2)
// ----------------------------------------------------------------------------
__global__ void __launch_bounds__(256) k_gemm(const float* __restrict__ A,
                                              const float* __restrict__ W,
                                              const float* __restrict__ bias,
                                              float* __restrict__ C,
                                              const float* __restrict__ scale,
                                              const int* __restrict__ rowidx,
                                              int m) {
    __shared__ __align__(16) float sW[128 * 64];
    const int tid = threadIdx.x;
    const int row0 = blockIdx.x * 128;
    const int col0 = blockIdx.y * 64;

    #pragma unroll 4
    for (int i = tid; i < 128 * 16; i += 256) {
        int r = i >> 4, c = (i & 15) << 2;
        *(float4*)(sW + r * 64 + c) = *(const float4*)(W + r * DD + col0 + c);
    }
    __syncthreads();

    const int tx = tid & 7, ty = tid >> 3;
    const int cb = tx * 8;
    const int rb = ty * 4;

    int rowv[4]; float scv[4]; bool vl[4];
    #pragma unroll
    for (int r = 0; r < 4; r++) {
        int rl = row0 + rb + r;
        vl[r] = (rl < m);
        int row = vl[r] ? (rowidx ? rowidx[rl] : rl) : 0;
        rowv[r] = row;
        scv[r] = (scale && vl[r]) ? scale[row] : 1.f;
    }

    unsigned long long acc[4][4] = {};

    #pragma unroll 2
    for (int k0 = 0; k0 < 128; k0 += 4) {
        float av[4][4];
        #pragma unroll
        for (int r = 0; r < 4; r++) {
            float4 v = vl[r] ? *(const float4*)(A + (size_t)rowv[r] * DD + k0)
                             : make_float4(0.f, 0.f, 0.f, 0.f);
            av[r][0] = v.x; av[r][1] = v.y; av[r][2] = v.z; av[r][3] = v.w;
        }
        #pragma unroll
        for (int kk = 0; kk < 4; kk++) {
            ulonglong2 w0 = *(ulonglong2*)(sW + (k0 + kk) * 64 + cb);
            ulonglong2 w1 = *(ulonglong2*)(sW + (k0 + kk) * 64 + cb + 4);
            #pragma unroll
            for (int r = 0; r < 4; r++) {
                unsigned long long aa = pack2(av[r][kk]);
                acc[r][0] = fma2(aa, w0.x, acc[r][0]);
                acc[r][1] = fma2(aa, w0.y, acc[r][1]);
                acc[r][2] = fma2(aa, w1.x, acc[r][2]);
                acc[r][3] = fma2(aa, w1.y, acc[r][3]);
            }
        }
    }

    float4 b0 = *(const float4*)(bias + col0 + cb);
    float4 b1 = *(const float4*)(bias + col0 + cb + 4);
    #pragma unroll
    for (int r = 0; r < 4; r++) {
        if (vl[r]) {
            float s = scv[r];
            float2 p0 = unpack2(acc[r][0]);
            float2 p1 = unpack2(acc[r][1]);
            float2 p2 = unpack2(acc[r][2]);
            float2 p3 = unpack2(acc[r][3]);
            float4 o0 = make_float4(fmaf(s, p0.x, b0.x), fmaf(s, p0.y, b0.y),
                                    fmaf(s, p1.x, b0.z), fmaf(s, p1.y, b0.w));
            float4 o1 = make_float4(fmaf(s, p2.x, b1.x), fmaf(s, p2.y, b1.y),
                                    fmaf(s, p3.x, b1.z), fmaf(s, p3.y, b1.w));
            float* cp = C + (size_t)rowv[r] * DD + col0 + cb;
            *(float4*)(cp)     = o0;
            *(float4*)(cp + 4) = o1;
        }
    }
}

// ----------------------------------------------------------------------------
// TopK: 48-bit keys (score<<16 | (65535-v)), 3 radix passes of 16 bits.
// keys fused with pass-0 count; parallel 64-block scan; apply+compact.
// ----------------------------------------------------------------------------
__global__ void k_keys(int kval) {
    int v = blockIdx.x * blockDim.x + threadIdx.x;
    if (v == 0) { g_prefix = 0ull; g_k = kval; }
    if (v >= NN) return;
    float s = (g_node[v].x > 0.f) ? g_score[v] : __int_as_float(0xff800000);
    unsigned u = __float_as_uint(s);
    u = (u & 0x80000000u) ? ~u : (u | 0x80000000u);
    unsigned long long key = ((unsigned long long)u << 16) |
                             (unsigned long long)(65535u - (unsigned)v);
    g_key[v] = key;
    atomicAdd(&g_hist[(unsigned)(key >> 32)], 1u);   // pass-0 count fused
}

__global__ void k_count(int pass) {   // pass in {1,2}
    int v = blockIdx.x * blockDim.x + threadIdx.x;
    if (v >= NN) return;
    unsigned long long key = g_key[v];
    if ((key >> (48 - 16 * pass)) != g_prefix) return;
    unsigned d = (unsigned)(key >> (32 - 16 * pass)) & 0xFFFFu;
    atomicAdd(&g_hist[d], 1u);
}

// parallel radix-select scan: SCAN_GRID blocks x 256 threads
__global__ void __launch_bounds__(256) k_scanp() {
    __shared__ unsigned red[256];
    __shared__ unsigned sf[256];
    __shared__ int sel_b;
    __shared__ unsigned sel_cum;
    int b = blockIdx.x, t = threadIdx.x;
    int base = b * 1024;

    unsigned s = 0;
    #pragma unroll
    for (int i = 0; i < 4; i++) s += g_hist[base + t + i * 256];
    red[t] = s;
    __syncthreads();
    for (int o = 128; o; o >>= 1) { if (t < o) red[t] += red[t + o]; __syncthreads(); }
    if (t == 0) g_part2[b] = red[0];
    gridbar();

    if (b == 0) {
        if (t == 0) {
            unsigned k = (unsigned)g_k;
            unsigned cum = 0;
            int bb = 0;
            for (bb = SCAN_GRID - 1; bb > 0; bb--) {
                unsigned p = g_part2[bb];
                if (cum + p >= k) break;
                cum += p;
            }
            sel_b = bb;
            sel_cum = cum;
        }
        __syncthreads();
        int bb = sel_b;
        unsigned kk = (unsigned)g_k - sel_cum;
        int sbase = bb * 1024 + t * 4;
        unsigned h0 = g_hist[sbase], h1 = g_hist[sbase + 1];
        unsigned h2 = g_hist[sbase + 2], h3 = g_hist[sbase + 3];
        unsigned gs = h0 + h1 + h2 + h3;
        sf[t] = gs;
        __syncthreads();
        for (int off = 1; off < 256; off <<= 1) {
            unsigned v = sf[t];
            unsigned ad = (t + off < 256) ? sf[t + off] : 0u;
            __syncthreads();
            sf[t] = v + ad;
            __syncthreads();
        }
        unsigned above = (t < 255) ? sf[t + 1] : 0u;
        if (above < kk && sf[t] >= kk) {
            unsigned cum = above;
            int d = sbase;
            if (cum + h3 >= kk)              { d = sbase + 3; }
            else if (cum + h3 + h2 >= kk)    { cum += h3; d = sbase + 2; }
            else if (cum + h3 + h2 + h1 >= kk){ cum += h3 + h2; d = sbase + 1; }
            else                             { cum += h3 + h2 + h1; d = sbase; }
            g_prefix = (g_prefix << 16) | (unsigned long long)(unsigned)d;
            g_k = (int)(kk - cum);
        }
    }
    gridbar();

    #pragma unroll
    for (int i = 0; i < 4; i++) g_hist[base + t + i * 256] = 0u;
}

__global__ void k_applynode(int* __restrict__ act, int* __restrict__ acnt) {
    int v = blockIdx.x * blockDim.x + threadIdx.x;
    if (v >= NN) return;
    bool kept = (g_key[v] >= g_prefix);
    float4 n4 = g_node[v];
    g_w[v] = kept ? n4.w : 0.f;
    g_s[v] = kept ? tanhf(g_score[v]) : 0.f;
    n4.x = kept ? 1.f : 0.f;
    g_node[v] = n4;
    if (kept) {
        int slot = atomicAdd(acnt, 1);
        act[slot] = v;
    }
}

// ----------------------------------------------------------------------------
// Host orchestration
// ----------------------------------------------------------------------------
extern "C" void kernel_launch(void* const* d_in, const int* in_sizes, int n_in,
                              void* d_out, int out_size) {
    const float* x_in = (const float*)d_in[0];
    const int*   ei   = (const int*)d_in[1];
    const float* Wd   = (const float*)d_in[2];
    const float* bd   = (const float*)d_in[3];
    const float* Wu   = (const float*)d_in[4];
    const float* bu   = (const float*)d_in[5];
    const float* Wb   = (const float*)d_in[6];
    const float* bb   = (const float*)d_in[7];
    const float* pvec = (const float*)d_in[8];
    float* out = (float*)d_out;

    float *p_h, *p_t, *p_g, *p_x, *p_d0, *p_d1;
    float *p_ecc0, *p_ecc1, *p_ecc2, *p_ctc0, *p_ctc1, *p_ctr0, *p_ctr1, *p_s;
    int *p_offr, *p_offc, *p_nbrr, *p_nbrc, *p_act0, *p_act1, *p_acnt0, *p_acnt1;
    cudaGetSymbolAddress((void**)&p_h, g_h);
    cudaGetSymbolAddress((void**)&p_t, g_t);
    cudaGetSymbolAddress((void**)&p_g, g_g);
    cudaGetSymbolAddress((void**)&p_x, g_xx);
    cudaGetSymbolAddress((void**)&p_d0, g_d0);
    cudaGetSymbolAddress((void**)&p_d1, g_d1);
    cudaGetSymbolAddress((void**)&p_ecc0, g_ecc0);
    cudaGetSymbolAddress((void**)&p_ecc1, g_ecc1);
    cudaGetSymbolAddress((void**)&p_ecc2, g_ecc2);
    cudaGetSymbolAddress((void**)&p_ctc0, g_ctc0);
    cudaGetSymbolAddress((void**)&p_ctc1, g_ctc1);
    cudaGetSymbolAddress((void**)&p_ctr0, g_ctr0);
    cudaGetSymbolAddress((void**)&p_ctr1, g_ctr1);
    cudaGetSymbolAddress((void**)&p_s, g_s);
    cudaGetSymbolAddress((void**)&p_offr, g_offr);
    cudaGetSymbolAddress((void**)&p_offc, g_offc);
    cudaGetSymbolAddress((void**)&p_nbrr, g_nbrr);
    cudaGetSymbolAddress((void**)&p_nbrc, g_nbrc);
    cudaGetSymbolAddress((void**)&p_act0, g_act0);
    cudaGetSymbolAddress((void**)&p_act1, g_act1);
    cudaGetSymbolAddress((void**)&p_acnt0, g_acnt0);
    cudaGetSymbolAddress((void**)&p_acnt1, g_acnt1);

    const int G_N    = (NN + TB - 1) / TB;      // 196
    const int G_NW   = (NN * 32) / TB;          // 6250  (full gather)
    const int G_NW1  = (K1 * 32) / TB;          // 3125  (act0 gather)
    const int G_NW2  = (K2 * 32 + TB - 1) / TB; // 1563  (act1 gather)
    const dim3 G_GF((NN + 127) / 128, 2);       // 391 x 2
    const dim3 G_G1((K1 + 127) / 128, 2);       // 196 x 2
    const dim3 G_G2((K2 + 127) / 128, 2);       // 98 x 2

    // ---- prefix: init+hist(1), gemm(2), scanfill(3), prep0(4 = profiled) ----
    k_init_hist<<<PREP_GRID, TB>>>(pvec, ei);                                 // #1
    k_gemm<<<G_GF, TB>>>(x_in, Wd, bd, p_t, nullptr, nullptr, NN);            // #2
    k_scanfill<<<PREP_GRID, TB>>>(ei);                                        // #3
    k_prep<<<PREP_GRID, TB>>>(p_ecc0, p_ctc0, p_ctr0);                        // #4 (profiled)

    // ---- down level 0 (dense) ----
    k_gather_t<false,false,false><<<G_NW, TB>>>(p_t, p_g, p_offc, p_nbrc, p_ecc0,
                                                nullptr, nullptr, 0, nullptr, NN);
    k_gemm<<<G_GF, TB>>>(p_g, Wd + (size_t)1*DD*DD, bd + 1*DD, p_t,
                         nullptr, nullptr, NN);
    k_gather_t<false,false,false><<<G_NW, TB>>>(p_t, p_d0, p_offc, p_nbrc, p_ecc0,
                                                nullptr, nullptr, 0, nullptr, NN);
    k_gather_t<false,false,true><<<G_NW, TB>>>(p_d0, p_h, p_offc, p_nbrc, p_ctc0,
                                               nullptr, pvec, 0, nullptr, NN);
    k_keys<<<G_N, TB>>>(K1);
    k_scanp<<<SCAN_GRID, 256>>>();
    for (int p = 1; p < 3; p++) { k_count<<<G_N, TB>>>(p); k_scanp<<<SCAN_GRID, 256>>>(); }
    k_applynode<<<G_N, TB>>>(p_act0, p_acnt0);

    // ---- down level 1 (sparse; act0-compacted where legal) ----
    k_gemm<<<G_G1, TB>>>(p_h, Wd + (size_t)2*DD*DD, bd + 2*DD, p_t,
                         p_s, p_act0, K1);
    k_prep<<<PREP_GRID, TB>>>(p_ecc1, p_ctc1, p_ctr1);
    k_gather_t<true,false,false><<<G_NW1, TB>>>(p_t, p_g, p_offc, p_nbrc, p_ecc1,
                                                nullptr, nullptr, 0, p_act0, K1);
    k_gemm<<<G_G1, TB>>>(p_g, Wd + (size_t)3*DD*DD, bd + 3*DD, p_t,
                         nullptr, p_act0, K1);
    // d1 must be dense-valid (read as dense addin later) -> full gather
    k_gather_t<true,false,false><<<G_NW, TB>>>(p_t, p_d1, p_offc, p_nbrc, p_ecc1,
                                               nullptr, nullptr, 0, nullptr, NN);
    k_gather_t<true,false,true><<<G_NW1, TB>>>(p_d1, p_h, p_offc, p_nbrc, p_ctc1,
                                               nullptr, pvec + DD, 1, p_act0, K1);
    k_keys<<<G_N, TB>>>(K2);
    k_scanp<<<SCAN_GRID, 256>>>();
    for (int p = 1; p < 3; p++) { k_count<<<G_N, TB>>>(p); k_scanp<<<SCAN_GRID, 256>>>(); }
    k_applynode<<<G_N, TB>>>(p_act1, p_acnt1);

    // ---- bottom ----
    k_gemm<<<G_G2, TB>>>(p_h, Wb, bb, p_t, p_s, p_act1, K2);
    k_prep<<<PREP_GRID, TB>>>(p_ecc2, nullptr, nullptr);
    k_gather_t<true,false,false><<<G_NW2, TB>>>(p_t, p_g, p_offc, p_nbrc, p_ecc2,
                                                nullptr, nullptr, 0, p_act1, K2);
    k_gemm<<<G_G2, TB>>>(p_g, Wb + (size_t)1*DD*DD, bb + 1*DD, p_t,
                         nullptr, p_act1, K2);
    // x must be valid for all act0 nodes (read by ctr1 gather) -> act0 list
    k_gather_t<true,false,false><<<G_NW1, TB>>>(p_t, p_x, p_offc, p_nbrc, p_ecc2,
                                                nullptr, nullptr, 0, p_act0, K1);

    // ---- up level 0 (act0 domain) ----
    k_gather_t<true,false,false><<<G_NW1, TB>>>(p_x, p_h, p_offr, p_nbrr, p_ctr1,
                                                nullptr, nullptr, 0, p_act0, K1);
    k_gemm<<<G_G1, TB>>>(p_h, Wu, bu, p_t, nullptr, p_act0, K1);
    k_gather_t<true,false,false><<<G_NW1, TB>>>(p_t, p_g, p_offc, p_nbrc, p_ecc1,
                                                nullptr, nullptr, 0, p_act0, K1);
    k_gemm<<<G_G1, TB>>>(p_g, Wu + (size_t)1*DD*DD, bu + 1*DD, p_t,
                         nullptr, p_act0, K1);
    // x = gather + d1 must be dense-valid (read by dense ctr0 gather) -> full
    k_gather_t<true,true,false><<<G_NW, TB>>>(p_t, p_x, p_offc, p_nbrc, p_ecc1,
                                              p_d1, nullptr, 0, nullptr, NN);

    // ---- up level 1 (dense, full graph) ----
    k_gather_t<false,false,false><<<G_NW, TB>>>(p_x, p_h, p_offr, p_nbrr, p_ctr0,
                                                nullptr, nullptr, 0, nullptr, NN);
    k_gemm<<<G_GF, TB>>>(p_h, Wu + (size_t)2*DD*DD, bu + 2*DD, p_t,
                         nullptr, nullptr, NN);
    k_gather_t<false,false,false><<<G_NW, TB>>>(p_t, p_g, p_offc, p_nbrc, p_ecc0,
                                                nullptr, nullptr, 0, nullptr, NN);
    k_gemm<<<G_GF, TB>>>(p_g, Wu + (size_t)3*DD*DD, bu + 3*DD, p_t,
                         nullptr, nullptr, NN);
    k_gather_t<false,true,false><<<G_NW, TB>>>(p_t, out, p_offc, p_nbrc, p_ecc0,
                                               p_d0, nullptr, 0, nullptr, NN);
}